// round 15
// baseline (speedup 1.0000x reference)
#include <cuda_runtime.h>
#include <cuda_fp16.h>
#include <math.h>
#include <stdint.h>

#define BATCH 2
#define LSEQ 4096
#define DMODEL 2048
#define D3 (3*DMODEL)
#define ORDER 64
#define NFFT 8192
#define FFT_T 512
#define FFT_SMEM ((NFFT + 512) * (int)sizeof(float2))   // 69632 B

// ---------------------------------------------------------------------------
// Scratch (device globals)
// ---------------------------------------------------------------------------
__device__ __half g_u [(size_t)BATCH*LSEQ*D3];        // fp16 in_proj output
__device__ __half g_x0[(size_t)BATCH*DMODEL*LSEQ];    // fp16 gate
__device__ __half g_vg[(size_t)BATCH*DMODEL*LSEQ];    // fp16 v*x1
__device__ __half g_y [(size_t)BATCH*DMODEL*LSEQ];    // fp16 post-conv gated (B,D,L)
__device__ __half g_h [(size_t)LSEQ*ORDER];           // fp16 MLP hidden (L,64)
__device__ __half g_kh[(size_t)DMODEL*LSEQ];          // fp16 filter k pre-decay (D,L)
__device__ __half2 g_Kf[(size_t)DMODEL*NFFT];         // fp16 spectrum

__device__ __half g_a  [(size_t)BATCH*LSEQ*DMODEL];   // fp16 x (B,L,D)
__device__ __half g_w1 [(size_t)D3*DMODEL];
__device__ __half g_w2 [(size_t)DMODEL*DMODEL];
__device__ __half g_w3h[(size_t)DMODEL*ORDER];

// ---------------------------------------------------------------------------
// GEMM common
// ---------------------------------------------------------------------------
#define GK_CHUNK 64
#define ARR_BYTES 16384
#define STAGE_BYTES (2*ARR_BYTES)
#define NSTAGE 3
#define GM_SMEM (NSTAGE*STAGE_BYTES)          // 98304 (tn kernel)
// wide gemm_nn: A 16K | B 32K per stage
#define STG_W (ARR_BYTES + 2*ARR_BYTES)
#define GM_SMEM_W (NSTAGE*STG_W)              // 147456

__device__ __forceinline__ uint32_t sw_off(int r, int cseg) {
    return (uint32_t)(r * 128 + ((cseg ^ (r & 7)) << 4));
}
__device__ __forceinline__ uint32_t sw2(int r, int cs) {
    return (uint32_t)(r * 256 + ((cs ^ (r & 15)) << 4));
}

__device__ __forceinline__ void cpa16(uint32_t s, const void* g) {
    asm volatile("cp.async.cg.shared.global [%0], [%1], 16;" :: "r"(s), "l"(g));
}
#define CP_COMMIT() asm volatile("cp.async.commit_group;" ::: "memory")
#define CP_WAIT1()  asm volatile("cp.async.wait_group 1;" ::: "memory")
#define CP_WAIT0()  asm volatile("cp.async.wait_group 0;" ::: "memory")

#define LDSM_X4(r, addr) \
    asm volatile("ldmatrix.sync.aligned.m8n8.x4.shared.b16 {%0,%1,%2,%3}, [%4];" \
        : "=r"((r)[0]), "=r"((r)[1]), "=r"((r)[2]), "=r"((r)[3]) : "r"(addr))

#define LDSM_X4T(r, addr) \
    asm volatile("ldmatrix.sync.aligned.m8n8.x4.trans.shared.b16 {%0,%1,%2,%3}, [%4];" \
        : "=r"((r)[0]), "=r"((r)[1]), "=r"((r)[2]), "=r"((r)[3]) : "r"(addr))

#define MMA16816(c, a, b) \
    asm volatile("mma.sync.aligned.m16n8k16.row.col.f32.f16.f16.f32 " \
        "{%0,%1,%2,%3}, {%4,%5,%6,%7}, {%8,%9}, {%0,%1,%2,%3};" \
        : "+f"((c)[0]), "+f"((c)[1]), "+f"((c)[2]), "+f"((c)[3]) \
        : "r"((a)[0]), "r"((a)[1]), "r"((a)[2]), "r"((a)[3]), \
          "r"((b)[0]), "r"((b)[1]))

// ---------------------------------------------------------------------------
// GEMM 1: 128(M) x 256(N) tile, 512 threads (warps 4x4), fp16 out
// ---------------------------------------------------------------------------
__global__ void __launch_bounds__(512, 1)
gemm_nn_kernel(const __half* __restrict__ A, const __half* __restrict__ W,
               const float* __restrict__ bias, __half* __restrict__ C,
               int Ntot, int K)
{
    extern __shared__ char smem[];
    const uint32_t sbase = (uint32_t)__cvta_generic_to_shared(smem);
    const int tid  = threadIdx.x;
    const int lane = tid & 31;
    const int wid  = tid >> 5;      // 0..15
    const int wm   = wid & 3;
    const int wn   = wid >> 2;      // 0..3

    const int col0 = blockIdx.x * 256;
    const int row0 = blockIdx.y * 128;
    const int nchunk = K / GK_CHUNK;

    float acc[2][8][4];
#pragma unroll
    for (int i = 0; i < 2; i++)
#pragma unroll
        for (int j = 0; j < 8; j++)
#pragma unroll
            for (int q = 0; q < 4; q++) acc[i][j][q] = 0.f;

    auto load_stage = [&](int slot, int k0) {
        const uint32_t sb = sbase + (uint32_t)(slot * STG_W);
#pragma unroll
        for (int i = 0; i < 2; i++) {                       // A: 1024 segs
            const int seg = tid + i * 512;
            const int r = seg >> 3, c = seg & 7;
            cpa16(sb + sw_off(r, c), A + (size_t)(row0 + r) * K + k0 + c * 8);
        }
#pragma unroll
        for (int i = 0; i < 4; i++) {                       // B: 2048 segs
            const int seg = tid + i * 512;
            const int r = seg >> 3, c = seg & 7;
            cpa16(sb + ARR_BYTES + sw_off(r, c), W + (size_t)(col0 + r) * K + k0 + c * 8);
        }
    };

    load_stage(0, 0);        CP_COMMIT();
    load_stage(1, GK_CHUNK); CP_COMMIT();

    const int a_row  = lane & 15;
    const int a_half = lane >> 4;
    const int b_row  = (((lane >> 3) & 3) >> 1) * 8 + (lane & 7);
    const int b_half = (lane >> 3) & 1;

    int slot = 0;
    for (int c = 0; c < nchunk; c++) {
        CP_WAIT1();
        __syncthreads();
        if (c + 2 < nchunk) {
            const int nslot = (slot + 2 >= NSTAGE) ? (slot + 2 - NSTAGE) : (slot + 2);
            load_stage(nslot, (c + 2) * GK_CHUNK);
        }
        CP_COMMIT();

        const uint32_t stb = sbase + (uint32_t)(slot * STG_W);
#pragma unroll
        for (int step = 0; step < 4; step++) {
            uint32_t af[2][4];
#pragma unroll
            for (int mt = 0; mt < 2; mt++) {
                const int r = wm*32 + mt*16 + a_row;
                LDSM_X4(af[mt], stb + sw_off(r, step*2 + a_half));
            }
            uint32_t bf[8][2];
#pragma unroll
            for (int p = 0; p < 4; p++) {
                const int r = wn*64 + p*16 + b_row;
                uint32_t t[4];
                LDSM_X4(t, stb + ARR_BYTES + sw_off(r, step*2 + b_half));
                bf[p*2][0]=t[0]; bf[p*2][1]=t[1]; bf[p*2+1][0]=t[2]; bf[p*2+1][1]=t[3];
            }
#pragma unroll
            for (int mt = 0; mt < 2; mt++)
#pragma unroll
                for (int nt = 0; nt < 8; nt++)
                    MMA16816(acc[mt][nt], af[mt], bf[nt]);
        }
        slot = (slot + 1 == NSTAGE) ? 0 : slot + 1;
    }

#pragma unroll
    for (int mt = 0; mt < 2; mt++) {
        const int r0g = row0 + wm*32 + mt*16 + (lane >> 2);
#pragma unroll
        for (int nt = 0; nt < 8; nt++) {
            const int col = col0 + wn*64 + nt*8 + (lane & 3)*2;
            const float b0 = bias[col], b1 = bias[col+1];
            *(__half2*)(C + (size_t)r0g       * Ntot + col) =
                __floats2half2_rn(acc[mt][nt][0] + b0, acc[mt][nt][1] + b1);
            *(__half2*)(C + (size_t)(r0g + 8) * Ntot + col) =
                __floats2half2_rn(acc[mt][nt][2] + b0, acc[mt][nt][3] + b1);
        }
    }
}

// ---------------------------------------------------------------------------
// GEMM 2: A stored transposed (K=d rows, M=l cols) fp16 (= g_y), trans-ldmatrix
// ---------------------------------------------------------------------------
__global__ void __launch_bounds__(256, 2)
gemm_tn_kernel(const __half* __restrict__ At, const __half* __restrict__ W,
               const float* __restrict__ bias, float* __restrict__ C,
               int Ntot, int K, size_t strideA, size_t strideC)
{
    extern __shared__ char smem[];
    const uint32_t sbase = (uint32_t)__cvta_generic_to_shared(smem);
    const int tid  = threadIdx.x;
    const int lane = tid & 31;
    const int wid  = tid >> 5;
    const int wm   = wid & 3;
    const int wn   = wid >> 2;

    const int z = blockIdx.z;
    const __half* Ab = At + (size_t)z * strideA;
    float* Cb = C + (size_t)z * strideC;

    const int col0 = blockIdx.x * 128;
    const int row0 = blockIdx.y * 128;
    const int nchunk = K / GK_CHUNK;

    float acc[2][8][4];
#pragma unroll
    for (int i = 0; i < 2; i++)
#pragma unroll
        for (int j = 0; j < 8; j++)
#pragma unroll
            for (int q = 0; q < 4; q++) acc[i][j][q] = 0.f;

    auto load_stage = [&](int slot, int k0) {
        const uint32_t sb = sbase + (uint32_t)(slot * STAGE_BYTES);
#pragma unroll
        for (int i = 0; i < 4; i++) {
            const int seg = tid + i * 256;
            const int ra = seg >> 4, ca = seg & 15;
            cpa16(sb + sw2(ra, ca),
                  Ab + (size_t)(k0 + ra) * LSEQ + row0 + ca * 8);
            const int rb = seg >> 3, cb = seg & 7;
            cpa16(sb + ARR_BYTES + sw_off(rb, cb),
                  W + (size_t)(col0 + rb) * K + k0 + cb * 8);
        }
    };

    load_stage(0, 0);        CP_COMMIT();
    load_stage(1, GK_CHUNK); CP_COMMIT();

    const int at_row  = ((lane >> 4) << 3) + (lane & 7);
    const int at_cs   = (lane >> 3) & 1;
    const int b_row  = (((lane >> 3) & 3) >> 1) * 8 + (lane & 7);
    const int b_half = (lane >> 3) & 1;

    int slot = 0;
    for (int c = 0; c < nchunk; c++) {
        CP_WAIT1();
        __syncthreads();
        if (c + 2 < nchunk) {
            const int nslot = (slot + 2 >= NSTAGE) ? (slot + 2 - NSTAGE) : (slot + 2);
            load_stage(nslot, (c + 2) * GK_CHUNK);
        }
        CP_COMMIT();

        const uint32_t stb = sbase + (uint32_t)(slot * STAGE_BYTES);
#pragma unroll
        for (int step = 0; step < 4; step++) {
            uint32_t af[2][4];
#pragma unroll
            for (int mt = 0; mt < 2; mt++) {
                const int row = step*16 + at_row;
                const int cs  = ((wm*32 + mt*16) >> 3) + at_cs;
                LDSM_X4T(af[mt], stb + sw2(row, cs));
            }
            uint32_t bf[8][2];
#pragma unroll
            for (int p = 0; p < 4; p++) {
                const int r = wn*64 + p*16 + b_row;
                uint32_t t[4];
                LDSM_X4(t, stb + ARR_BYTES + sw_off(r, step*2 + b_half));
                bf[p*2][0]=t[0]; bf[p*2][1]=t[1]; bf[p*2+1][0]=t[2]; bf[p*2+1][1]=t[3];
            }
#pragma unroll
            for (int mt = 0; mt < 2; mt++)
#pragma unroll
                for (int nt = 0; nt < 8; nt++)
                    MMA16816(acc[mt][nt], af[mt], bf[nt]);
        }
        slot = (slot + 1 == NSTAGE) ? 0 : slot + 1;
    }

#pragma unroll
    for (int mt = 0; mt < 2; mt++) {
        const int r0g = row0 + wm*32 + mt*16 + (lane >> 2);
#pragma unroll
        for (int nt = 0; nt < 8; nt++) {
            const int col = col0 + wn*64 + nt*8 + (lane & 3)*2;
            const float b0 = bias[col], b1 = bias[col+1];
            *(float2*)(Cb + (size_t)r0g       * Ntot + col) =
                make_float2(acc[mt][nt][0] + b0, acc[mt][nt][1] + b1);
            *(float2*)(Cb + (size_t)(r0g + 8) * Ntot + col) =
                make_float2(acc[mt][nt][2] + b0, acc[mt][nt][3] + b1);
        }
    }
}

// ---------------------------------------------------------------------------
// k-GEMM: g_kh[d,l] = dot(w3h[d,:64], g_h[l,:64]) — single K=64 stage, fp16 out
// ---------------------------------------------------------------------------
__global__ void __launch_bounds__(256, 2)
kgemm_kernel()
{
    __shared__ char smem[2 * ARR_BYTES];
    const uint32_t sbase = (uint32_t)__cvta_generic_to_shared(smem);
    const int tid  = threadIdx.x;
    const int lane = tid & 31;
    const int wid  = tid >> 5;
    const int wm   = wid & 3;
    const int wn   = wid >> 2;

    const int col0 = blockIdx.x * 128;   // l
    const int row0 = blockIdx.y * 128;   // d

#pragma unroll
    for (int i = 0; i < 4; i++) {
        const int seg = tid + i * 256;
        const int r = seg >> 3, c = seg & 7;
        const uint32_t so = sw_off(r, c);
        cpa16(sbase + so,             g_w3h + (size_t)(row0 + r) * ORDER + c * 8);
        cpa16(sbase + so + ARR_BYTES, g_h   + (size_t)(col0 + r) * ORDER + c * 8);
    }
    CP_COMMIT();
    CP_WAIT0();
    __syncthreads();

    float acc[2][8][4];
#pragma unroll
    for (int i = 0; i < 2; i++)
#pragma unroll
        for (int j = 0; j < 8; j++)
#pragma unroll
            for (int q = 0; q < 4; q++) acc[i][j][q] = 0.f;

    const int a_row  = lane & 15;
    const int a_half = lane >> 4;
    const int b_row  = (((lane >> 3) & 3) >> 1) * 8 + (lane & 7);
    const int b_half = (lane >> 3) & 1;

#pragma unroll
    for (int step = 0; step < 4; step++) {
        uint32_t af[2][4];
#pragma unroll
        for (int mt = 0; mt < 2; mt++) {
            const int r = wm*32 + mt*16 + a_row;
            LDSM_X4(af[mt], sbase + sw_off(r, step*2 + a_half));
        }
        uint32_t bf[8][2];
#pragma unroll
        for (int p = 0; p < 4; p++) {
            const int r = wn*64 + p*16 + b_row;
            uint32_t t[4];
            LDSM_X4(t, sbase + ARR_BYTES + sw_off(r, step*2 + b_half));
            bf[p*2][0]=t[0]; bf[p*2][1]=t[1]; bf[p*2+1][0]=t[2]; bf[p*2+1][1]=t[3];
        }
#pragma unroll
        for (int mt = 0; mt < 2; mt++)
#pragma unroll
            for (int nt = 0; nt < 8; nt++)
                MMA16816(acc[mt][nt], af[mt], bf[nt]);
    }

#pragma unroll
    for (int mt = 0; mt < 2; mt++) {
        const int d = row0 + wm*32 + mt*16 + (lane >> 2);
#pragma unroll
        for (int nt = 0; nt < 8; nt++) {
            const int l = col0 + wn*64 + nt*8 + (lane & 3)*2;
            *(__half2*)(g_kh + (size_t)d       * LSEQ + l) =
                __floats2half2_rn(acc[mt][nt][0], acc[mt][nt][1]);
            *(__half2*)(g_kh + (size_t)(d + 8) * LSEQ + l) =
                __floats2half2_rn(acc[mt][nt][2], acc[mt][nt][3]);
        }
    }
}

// ---------------------------------------------------------------------------
// merged fp32 -> fp16 convert (4 ranges, 1 launch)
// ---------------------------------------------------------------------------
__global__ void __launch_bounds__(256)
tohalf4_kernel(const float4* __restrict__ s0, __half2* __restrict__ d0, int n0,
               const float4* __restrict__ s1, __half2* __restrict__ d1, int n1,
               const float4* __restrict__ s2, __half2* __restrict__ d2, int n2,
               const float4* __restrict__ s3, __half2* __restrict__ d3, int n3)
{
    int i = blockIdx.x * 256 + threadIdx.x;
    const float4* s; __half2* d;
    if (i < n0) { s = s0; d = d0; }
    else if (i < n0 + n1) { i -= n0; s = s1; d = d1; }
    else if (i < n0 + n1 + n2) { i -= n0 + n1; s = s2; d = d2; }
    else if (i < n0 + n1 + n2 + n3) { i -= n0 + n1 + n2; s = s3; d = d3; }
    else return;
    const float4 v = s[i];
    d[i*2+0] = __floats2half2_rn(v.x, v.y);
    d[i*2+1] = __floats2half2_rn(v.z, v.w);
}

// ---------------------------------------------------------------------------
// Short conv + transpose + gate (fp16 in/out; fp32 math)
// ---------------------------------------------------------------------------
__global__ void __launch_bounds__(256)
shortconv_kernel(const float* __restrict__ sw, const float* __restrict__ sb)
{
    __shared__ float su[3][34][33];
    const int b = blockIdx.z, l0 = blockIdx.x * 32, d0 = blockIdx.y * 32;
    const int tx = threadIdx.x, ty = threadIdx.y;

#pragma unroll
    for (int g = 0; g < 3; g++)
        for (int li = ty; li < 34; li += 8) {
            const int l = l0 + li - 2;
            su[g][li][tx] = (l >= 0)
                ? __half2float(g_u[((size_t)b * LSEQ + l) * D3 + g * DMODEL + d0 + tx]) : 0.f;
        }
    __syncthreads();

    const int l = l0 + tx;
    for (int di = ty; di < 32; di += 8) {
        const int d = d0 + di;
        float r[3];
#pragma unroll
        for (int g = 0; g < 3; g++) {
            const int c = g * DMODEL + d;
            r[g] = sw[c*3+0] * su[g][tx][di]
                 + sw[c*3+1] * su[g][tx+1][di]
                 + sw[c*3+2] * su[g][tx+2][di]
                 + sb[c];
        }
        const size_t o = ((size_t)b * DMODEL + d) * LSEQ + l;
        g_x0[o] = __float2half_rn(r[0]);
        g_vg[o] = __float2half_rn(r[1] * r[2]);
    }
}

// ---------------------------------------------------------------------------
// Filter MLP hidden state h (L,64) -> fp16
// ---------------------------------------------------------------------------
__global__ void __launch_bounds__(256)
filter_h_kernel(const float* __restrict__ w0, const float* __restrict__ b0,
                const float* __restrict__ freq,
                const float* __restrict__ w1, const float* __restrict__ b1,
                const float* __restrict__ w2, const float* __restrict__ b2)
{
    __shared__ float ws[ORDER][ORDER + 1];
    __shared__ float h1[4][ORDER + 1];
    const int o  = threadIdx.x;
    const int lq = threadIdx.y;
    const int l  = blockIdx.x * 4 + lq;
    const int tid = lq * ORDER + o;

    const float t   = (float)l / (float)(LSEQ - 1);
    const float ang = 1e-4f * (2.f * 3.14159265358979323846f * (float)l / (float)LSEQ);
    const float fr = freq[o];
    float v = t * w0[o*3+0] + __cosf(ang) * w0[o*3+1] - __sinf(ang) * w0[o*3+2] + b0[o];
    h1[lq][o] = __sinf(fr * v);
    for (int i = tid; i < ORDER * ORDER; i += 256) ws[i >> 6][i & 63] = w1[i];
    __syncthreads();

    float s = b1[o];
#pragma unroll 8
    for (int j = 0; j < ORDER; j++) s = fmaf(ws[o][j], h1[lq][j], s);
    const float h2v = __sinf(fr * s);
    __syncthreads();

    h1[lq][o] = h2v;
    for (int i = tid; i < ORDER * ORDER; i += 256) ws[i >> 6][i & 63] = w2[i];
    __syncthreads();

    s = b2[o];
#pragma unroll 8
    for (int j = 0; j < ORDER; j++) s = fmaf(ws[o][j], h1[lq][j], s);
    g_h[(size_t)l * ORDER + o] = __float2half_rn(__sinf(fr * s));
}

// ---------------------------------------------------------------------------
// N=8192 in-place FFT (single smem buffer), XOR swizzle
// ---------------------------------------------------------------------------
#define SQ(w) ((w) ^ (((w) >> 4) & 15))

__device__ __forceinline__ float2 cmul(float2 a, float2 b) {
    return make_float2(a.x*b.x - a.y*b.y, a.x*b.y + a.y*b.x);
}

__device__ __forceinline__ void fft_init_tw(float2* tw)
{
    for (int i = threadIdx.x; i < 512; i += FFT_T) {
        float s, c;
        sincosf(-2.f * 3.14159265358979323846f * (float)i / (float)NFFT, &s, &c);
        tw[i] = make_float2(c, s);
    }
}

#define CMC(v, wr, wi) do { float _x=(v).x, _y=(v).y; \
    (v).x = _x*(wr) - _y*(wi); (v).y = _x*(wi) + _y*(wr); } while (0)

__device__ __forceinline__ void bf4(float2& a, float2& b, float2& c, float2& d)
{
    const float2 A = make_float2(a.x + c.x, a.y + c.y);
    const float2 B = make_float2(a.x - c.x, a.y - c.y);
    const float2 Cc = make_float2(b.x + d.x, b.y + d.y);
    const float2 D = make_float2(b.x - d.x, b.y - d.y);
    a = make_float2(A.x + Cc.x, A.y + Cc.y);
    c = make_float2(A.x - Cc.x, A.y - Cc.y);
    b = make_float2(B.x + D.y, B.y - D.x);
    d = make_float2(B.x - D.y, B.y + D.x);
}

__device__ __forceinline__ void dft16(float2* x)
{
    bf4(x[0], x[4], x[8],  x[12]);
    bf4(x[1], x[5], x[9],  x[13]);
    bf4(x[2], x[6], x[10], x[14]);
    bf4(x[3], x[7], x[11], x[15]);
    const float C1 = 0.92387953251128674f, S1 = -0.38268343236508978f;
    const float C2 = 0.70710678118654757f, S2 = -0.70710678118654746f;
    const float C3 = 0.38268343236508984f, S3 = -0.92387953251128674f;
    const float C6 = -0.70710678118654746f, S6 = -0.70710678118654757f;
    const float C9 = -0.92387953251128674f, S9 =  0.38268343236508978f;
    CMC(x[5],  C1, S1);  CMC(x[9],  C2, S2);  CMC(x[13], C3, S3);
    CMC(x[6],  C2, S2);  { float tx = x[10].x; x[10].x = x[10].y; x[10].y = -tx; }  CMC(x[14], C6, S6);
    CMC(x[7],  C3, S3);  CMC(x[11], C6, S6);  CMC(x[15], C9, S9);
    bf4(x[0],  x[1],  x[2],  x[3]);
    bf4(x[4],  x[5],  x[6],  x[7]);
    bf4(x[8],  x[9],  x[10], x[11]);
    bf4(x[12], x[13], x[14], x[15]);
}

__device__ __forceinline__ void r16_stage_ip(float2* buf, const float2* tw, int m)
{
    const int t = threadIdx.x;
    const int k = t & (m - 1);
    const int jm = t - k;
    float2 x[16];
#pragma unroll
    for (int c = 0; c < 16; c++) x[c] = buf[SQ(t + 512 * c)];
    dft16(x);
    const float2 w1 = tw[jm];
    float2 wc = w1;
#pragma unroll
    for (int c = 1; c < 16; c++) {
        const int p = ((c & 3) << 2) | (c >> 2);
        x[p] = cmul(x[p], wc);
        wc = cmul(wc, w1);
    }
    __syncthreads();
    const int ob = 16 * jm + k;
#pragma unroll
    for (int c = 0; c < 16; c++)
        buf[SQ(ob + c * m)] = x[((c & 3) << 2) | (c >> 2)];
    __syncthreads();
}

__device__ __forceinline__ void fft8192_ip(float2* buf, const float2* tw)
{
    __syncthreads();
    r16_stage_ip(buf, tw, 1);
    r16_stage_ip(buf, tw, 16);
    r16_stage_ip(buf, tw, 256);
    const int t = threadIdx.x;
    float2 a[8], b[8];
#pragma unroll
    for (int c = 0; c < 8; c++) {
        const int i = t + 512 * c;
        a[c] = buf[SQ(i)];
        b[c] = buf[SQ(i + 4096)];
    }
    __syncthreads();
#pragma unroll
    for (int c = 0; c < 8; c++) {
        const int i = t + 512 * c;
        buf[SQ(i)]        = make_float2(a[c].x + b[c].x, a[c].y + b[c].y);
        buf[SQ(i + 4096)] = make_float2(a[c].x - b[c].x, a[c].y - b[c].y);
    }
    __syncthreads();
}

// FFT of filter k (applies ExponentialModulation decay at load)
__global__ void __launch_bounds__(FFT_T, 2) fftk_kernel()
{
    extern __shared__ float2 smem_fft[];
    float2* buf = smem_fft;
    float2* tw  = buf + NFFT;
    fft_init_tw(tw);

    const int d0 = blockIdx.x * 2;
    const __half* k0 = g_kh + (size_t)d0 * LSEQ;
    const __half* k1 = k0 + LSEQ;
    const float min_decay = -4.60517018598809136804f / 1.5f;
    const float max_decay = -4.60517018598809136804f / 0.3f;
    const float ad0 = fabsf(min_decay + (max_decay - min_decay) * (float)d0 / (float)(DMODEL - 1));
    const float ad1 = fabsf(min_decay + (max_decay - min_decay) * (float)(d0 + 1) / (float)(DMODEL - 1));

    for (int i = threadIdx.x; i < LSEQ; i += FFT_T) {
        const float t = (float)i / (float)(LSEQ - 1);
        buf[SQ(i)] = make_float2(__half2float(k0[i]) * __expf(-t * ad0),
                                 __half2float(k1[i]) * __expf(-t * ad1));
        buf[SQ(i + LSEQ)] = make_float2(0.f, 0.f);
    }
    fft8192_ip(buf, tw);

    const float hc = 0.5f / (float)NFFT;
    __half2* o0 = g_Kf + (size_t)d0 * NFFT;
    __half2* o1 = o0 + NFFT;
    for (int i = threadIdx.x; i < NFFT; i += FFT_T) {
        const int ir = (NFFT - i) & (NFFT - 1);
        const float2 A = buf[SQ(i)];
        const float2 Zr = buf[SQ(ir)];
        const float sx = A.x + Zr.x, sy = A.y - Zr.y;
        const float px = A.x - Zr.x, py = A.y + Zr.y;
        o0[i] = __floats2half2_rn(sx * hc, sy * hc);
        o1[i] = __floats2half2_rn(py * hc, -px * hc);
    }
}

__device__ __forceinline__ float2 pw_prod(float2 A, float2 B, float2 k)
{
    const float u0x = 0.5f * (A.x + B.x), u0y = 0.5f * (A.y - B.y);
    const float px  = 0.5f * (A.x - B.x), py  = 0.5f * (A.y + B.y);
    const float u1x = py, u1y = -px;
    const float y0x = u0x * k.x - u0y * k.y;
    const float y0y = u0x * k.y + u0y * k.x;
    const float y1x = u1x * k.x - u1y * k.y;
    const float y1y = u1x * k.y + u1y * k.x;
    return make_float2(y0x - y1y, -(y0y + y1x));
}

__global__ void __launch_bounds__(FFT_T, 2) fftconv_kernel(const float* __restrict__ fbias)
{
    extern __shared__ float2 smem_fft[];
    float2* buf = smem_fft;
    float2* tw  = buf + NFFT;
    fft_init_tw(tw);

    const int d = blockIdx.x;
    const __half* v0 = g_vg + (size_t)d * LSEQ;
    const __half* v1 = g_vg + ((size_t)DMODEL + d) * LSEQ;

    for (int i = threadIdx.x; i < LSEQ; i += FFT_T) {
        buf[SQ(i)]        = make_float2(__half2float(v0[i]), __half2float(v1[i]));
        buf[SQ(i + LSEQ)] = make_float2(0.f, 0.f);
    }
    fft8192_ip(buf, tw);

    const __half2* kf = g_Kf + (size_t)d * NFFT;
    const int t = threadIdx.x;
#pragma unroll 1
    for (int c = 0; c < 8; c++) {
        const int i  = t + 512 * c;
        const int ir = (NFFT - i) & (NFFT - 1);
        const float2 A = buf[SQ(i)];
        const float2 B = buf[SQ(ir)];
        buf[SQ(i)] = pw_prod(A, B, __half22float2(kf[i]));
        if (ir != i)
            buf[SQ(ir)] = pw_prod(B, A, __half22float2(kf[ir]));
    }
    if (t == 0) {
        const float2 A = buf[SQ(4096)];
        buf[SQ(4096)] = pw_prod(A, A, __half22float2(kf[4096]));
    }

    fft8192_ip(buf, tw);

    const float fb = fbias[d];
    for (int i = threadIdx.x; i < LSEQ; i += FFT_T) {
        const size_t o0 = (size_t)d * LSEQ + i;
        const size_t o1 = ((size_t)DMODEL + d) * LSEQ + i;
        const float2 r = buf[SQ(i)];
        const float x00 = __half2float(g_x0[o0]);
        const float x01 = __half2float(g_x0[o1]);
        g_y[o0] = __float2half_rn((r.x + __half2float(v0[i]) * fb) * x00);
        g_y[o1] = __float2half_rn((-r.y + __half2float(v1[i]) * fb) * x01);
    }
}

// ---------------------------------------------------------------------------
// Launch (single stream — allocation-free; 8 launches)
// ---------------------------------------------------------------------------
extern "C" void kernel_launch(void* const* d_in, const int* in_sizes, int n_in,
                              void* d_out, int out_size)
{
    (void)in_sizes; (void)n_in; (void)out_size;
    const float* x     = (const float*)d_in[0];
    const float* ipw   = (const float*)d_in[1];
    const float* ipb   = (const float*)d_in[2];
    const float* sw    = (const float*)d_in[3];
    const float* sb    = (const float*)d_in[4];
    const float* w0    = (const float*)d_in[5];
    const float* b0    = (const float*)d_in[6];
    const float* freq  = (const float*)d_in[7];
    const float* w1    = (const float*)d_in[8];
    const float* b1    = (const float*)d_in[9];
    const float* w2    = (const float*)d_in[10];
    const float* b2    = (const float*)d_in[11];
    const float* w3    = (const float*)d_in[12];
    const float* fbias = (const float*)d_in[13];
    const float* opw   = (const float*)d_in[14];
    const float* opb   = (const float*)d_in[15];
    float* out = (float*)d_out;

    cudaFuncSetAttribute(fftk_kernel,    cudaFuncAttributeMaxDynamicSharedMemorySize, FFT_SMEM);
    cudaFuncSetAttribute(fftconv_kernel, cudaFuncAttributeMaxDynamicSharedMemorySize, FFT_SMEM);
    cudaFuncSetAttribute(gemm_nn_kernel, cudaFuncAttributeMaxDynamicSharedMemorySize, GM_SMEM_W);
    cudaFuncSetAttribute(gemm_tn_kernel, cudaFuncAttributeMaxDynamicSharedMemorySize, GM_SMEM);

    __half *p_a, *p_w1, *p_w2, *p_w3, *p_u, *p_y;
    cudaGetSymbolAddress((void**)&p_a,  g_a);
    cudaGetSymbolAddress((void**)&p_w1, g_w1);
    cudaGetSymbolAddress((void**)&p_w2, g_w2);
    cudaGetSymbolAddress((void**)&p_w3, g_w3h);
    cudaGetSymbolAddress((void**)&p_u,  g_u);
    cudaGetSymbolAddress((void**)&p_y,  g_y);

    // 0) all fp32->fp16 conversions in one launch
    const int n4x  = (BATCH*LSEQ*DMODEL)/4;
    const int n4w1 = (D3*DMODEL)/4;
    const int n4w2 = (DMODEL*DMODEL)/4;
    const int n4w3 = (DMODEL*ORDER)/4;
    tohalf4_kernel<<<(n4x+n4w1+n4w2+n4w3+255)/256, 256>>>(
        (const float4*)x,   (__half2*)p_a,  n4x,
        (const float4*)ipw, (__half2*)p_w1, n4w1,
        (const float4*)opw, (__half2*)p_w2, n4w2,
        (const float4*)w3,  (__half2*)p_w3, n4w3);

    // 1) in_proj GEMM (wide tile, fp16 out)
    gemm_nn_kernel<<<dim3(D3/256, (BATCH*LSEQ)/128), 512, GM_SMEM_W>>>(
        p_a, p_w1, ipb, p_u, D3, DMODEL);

    // 2) short conv + transpose + gate
    shortconv_kernel<<<dim3(LSEQ/32, DMODEL/32, BATCH), dim3(32, 8)>>>(sw, sb);

    // 3) filter MLP hidden state (fp16)
    filter_h_kernel<<<LSEQ/4, dim3(ORDER, 4)>>>(w0, b0, freq, w1, b1, w2, b2);

    // 4) k-projection on tensor cores (K=64)
    kgemm_kernel<<<dim3(LSEQ/128, DMODEL/128), 256>>>();

    // 5) FFT of filter k (decay folded in)
    fftk_kernel<<<DMODEL/2, FFT_T, FFT_SMEM>>>();

    // 6) fused FFT conv + bias + output gate
    fftconv_kernel<<<DMODEL, FFT_T, FFT_SMEM>>>(fbias);

    // 7) out_proj GEMM reading g_y transposed
    gemm_tn_kernel<<<dim3(DMODEL/128, LSEQ/128, BATCH), 256, GM_SMEM>>>(
        p_y, p_w2, opb, out, DMODEL, DMODEL,
        (size_t)DMODEL*LSEQ, (size_t)LSEQ*DMODEL);
}

// round 16
// speedup vs baseline: 1.0824x; 1.0824x over previous
#include <cuda_runtime.h>
#include <cuda_fp16.h>
#include <math.h>
#include <stdint.h>

#define BATCH 2
#define LSEQ 4096
#define DMODEL 2048
#define D3 (3*DMODEL)
#define ORDER 64
#define NFFT 8192
#define FFT_T 512
#define FFT_SMEM ((NFFT + 512) * (int)sizeof(float2))   // 69632 B

// ---------------------------------------------------------------------------
// Scratch (device globals)
// ---------------------------------------------------------------------------
__device__ __half g_u [(size_t)BATCH*LSEQ*D3];        // fp16 in_proj output
__device__ __half g_x0[(size_t)BATCH*DMODEL*LSEQ];    // fp16 gate
__device__ __half g_vg[(size_t)BATCH*DMODEL*LSEQ];    // fp16 v*x1
__device__ __half g_y [(size_t)BATCH*DMODEL*LSEQ];    // fp16 post-conv gated (B,D,L)
__device__ __half g_h [(size_t)LSEQ*ORDER];           // fp16 MLP hidden (L,64)
__device__ __half g_kh[(size_t)DMODEL*LSEQ];          // fp16 filter k pre-decay (D,L)
__device__ __half2 g_Kf[(size_t)DMODEL*NFFT];         // fp16 spectrum

__device__ __half g_a  [(size_t)BATCH*LSEQ*DMODEL];   // fp16 x (B,L,D)
__device__ __half g_w1 [(size_t)D3*DMODEL];
__device__ __half g_w2 [(size_t)DMODEL*DMODEL];
__device__ __half g_w3h[(size_t)DMODEL*ORDER];

// ---------------------------------------------------------------------------
// GEMM common
// ---------------------------------------------------------------------------
#define GK_CHUNK 64
#define ARR_BYTES 16384
#define STAGE_BYTES (2*ARR_BYTES)
#define NSTAGE 3
#define GM_SMEM (NSTAGE*STAGE_BYTES)      // 98304 B

__device__ __forceinline__ uint32_t sw_off(int r, int cseg) {
    return (uint32_t)(r * 128 + ((cseg ^ (r & 7)) << 4));
}
__device__ __forceinline__ uint32_t sw2(int r, int cs) {
    return (uint32_t)(r * 256 + ((cs ^ (r & 15)) << 4));
}

__device__ __forceinline__ void cpa16(uint32_t s, const void* g) {
    asm volatile("cp.async.cg.shared.global [%0], [%1], 16;" :: "r"(s), "l"(g));
}
#define CP_COMMIT() asm volatile("cp.async.commit_group;" ::: "memory")
#define CP_WAIT1()  asm volatile("cp.async.wait_group 1;" ::: "memory")
#define CP_WAIT0()  asm volatile("cp.async.wait_group 0;" ::: "memory")

#define LDSM_X4(r, addr) \
    asm volatile("ldmatrix.sync.aligned.m8n8.x4.shared.b16 {%0,%1,%2,%3}, [%4];" \
        : "=r"((r)[0]), "=r"((r)[1]), "=r"((r)[2]), "=r"((r)[3]) : "r"(addr))

#define LDSM_X4T(r, addr) \
    asm volatile("ldmatrix.sync.aligned.m8n8.x4.trans.shared.b16 {%0,%1,%2,%3}, [%4];" \
        : "=r"((r)[0]), "=r"((r)[1]), "=r"((r)[2]), "=r"((r)[3]) : "r"(addr))

#define MMA16816(c, a, b) \
    asm volatile("mma.sync.aligned.m16n8k16.row.col.f32.f16.f16.f32 " \
        "{%0,%1,%2,%3}, {%4,%5,%6,%7}, {%8,%9}, {%0,%1,%2,%3};" \
        : "+f"((c)[0]), "+f"((c)[1]), "+f"((c)[2]), "+f"((c)[3]) \
        : "r"((a)[0]), "r"((a)[1]), "r"((a)[2]), "r"((a)[3]), \
          "r"((b)[0]), "r"((b)[1]))

// ---------------------------------------------------------------------------
// GEMM 1: A row-major (L,K) fp16 -> C fp16 (128x128, 256 thr, 2 CTAs/SM)
// ---------------------------------------------------------------------------
__global__ void __launch_bounds__(256, 2)
gemm_nn_kernel(const __half* __restrict__ A, const __half* __restrict__ W,
               const float* __restrict__ bias, __half* __restrict__ C,
               int Ntot, int K)
{
    extern __shared__ char smem[];
    const uint32_t sbase = (uint32_t)__cvta_generic_to_shared(smem);
    const int tid  = threadIdx.x;
    const int lane = tid & 31;
    const int wid  = tid >> 5;
    const int wm   = wid & 3;
    const int wn   = wid >> 2;

    const int col0 = blockIdx.x * 128;
    const int row0 = blockIdx.y * 128;
    const int nchunk = K / GK_CHUNK;

    float acc[2][8][4];
#pragma unroll
    for (int i = 0; i < 2; i++)
#pragma unroll
        for (int j = 0; j < 8; j++)
#pragma unroll
            for (int q = 0; q < 4; q++) acc[i][j][q] = 0.f;

    auto load_stage = [&](int slot, int k0) {
        const uint32_t sb = sbase + (uint32_t)(slot * STAGE_BYTES);
#pragma unroll
        for (int i = 0; i < 4; i++) {
            const int seg = tid + i * 256;
            const int r = seg >> 3, c = seg & 7;
            const uint32_t so = sw_off(r, c);
            cpa16(sb + so,             A + (size_t)(row0 + r) * K + k0 + c * 8);
            cpa16(sb + so + ARR_BYTES, W + (size_t)(col0 + r) * K + k0 + c * 8);
        }
    };

    load_stage(0, 0);        CP_COMMIT();
    load_stage(1, GK_CHUNK); CP_COMMIT();

    const int a_row  = lane & 15;
    const int a_half = lane >> 4;
    const int b_row  = (((lane >> 3) & 3) >> 1) * 8 + (lane & 7);
    const int b_half = (lane >> 3) & 1;

    int slot = 0;
    for (int c = 0; c < nchunk; c++) {
        CP_WAIT1();
        __syncthreads();
        if (c + 2 < nchunk) {
            const int nslot = (slot + 2 >= NSTAGE) ? (slot + 2 - NSTAGE) : (slot + 2);
            load_stage(nslot, (c + 2) * GK_CHUNK);
        }
        CP_COMMIT();

        const uint32_t stb = sbase + (uint32_t)(slot * STAGE_BYTES);
#pragma unroll
        for (int step = 0; step < 4; step++) {
            uint32_t af[2][4];
#pragma unroll
            for (int mt = 0; mt < 2; mt++) {
                const int r = wm*32 + mt*16 + a_row;
                LDSM_X4(af[mt], stb + sw_off(r, step*2 + a_half));
            }
            uint32_t bf[8][2];
#pragma unroll
            for (int p = 0; p < 4; p++) {
                const int r = wn*64 + p*16 + b_row;
                uint32_t t[4];
                LDSM_X4(t, stb + ARR_BYTES + sw_off(r, step*2 + b_half));
                bf[p*2][0]=t[0]; bf[p*2][1]=t[1]; bf[p*2+1][0]=t[2]; bf[p*2+1][1]=t[3];
            }
#pragma unroll
            for (int mt = 0; mt < 2; mt++)
#pragma unroll
                for (int nt = 0; nt < 8; nt++)
                    MMA16816(acc[mt][nt], af[mt], bf[nt]);
        }
        slot = (slot + 1 == NSTAGE) ? 0 : slot + 1;
    }

#pragma unroll
    for (int mt = 0; mt < 2; mt++) {
        const int r0g = row0 + wm*32 + mt*16 + (lane >> 2);
#pragma unroll
        for (int nt = 0; nt < 8; nt++) {
            const int col = col0 + wn*64 + nt*8 + (lane & 3)*2;
            const float b0 = bias[col], b1 = bias[col+1];
            *(__half2*)(C + (size_t)r0g       * Ntot + col) =
                __floats2half2_rn(acc[mt][nt][0] + b0, acc[mt][nt][1] + b1);
            *(__half2*)(C + (size_t)(r0g + 8) * Ntot + col) =
                __floats2half2_rn(acc[mt][nt][2] + b0, acc[mt][nt][3] + b1);
        }
    }
}

// ---------------------------------------------------------------------------
// GEMM 2: A stored transposed (K=d rows, M=l cols) fp16 (= g_y), trans-ldmatrix
// ---------------------------------------------------------------------------
__global__ void __launch_bounds__(256, 2)
gemm_tn_kernel(const __half* __restrict__ At, const __half* __restrict__ W,
               const float* __restrict__ bias, float* __restrict__ C,
               int Ntot, int K, size_t strideA, size_t strideC)
{
    extern __shared__ char smem[];
    const uint32_t sbase = (uint32_t)__cvta_generic_to_shared(smem);
    const int tid  = threadIdx.x;
    const int lane = tid & 31;
    const int wid  = tid >> 5;
    const int wm   = wid & 3;
    const int wn   = wid >> 2;

    const int z = blockIdx.z;
    const __half* Ab = At + (size_t)z * strideA;
    float* Cb = C + (size_t)z * strideC;

    const int col0 = blockIdx.x * 128;
    const int row0 = blockIdx.y * 128;
    const int nchunk = K / GK_CHUNK;

    float acc[2][8][4];
#pragma unroll
    for (int i = 0; i < 2; i++)
#pragma unroll
        for (int j = 0; j < 8; j++)
#pragma unroll
            for (int q = 0; q < 4; q++) acc[i][j][q] = 0.f;

    auto load_stage = [&](int slot, int k0) {
        const uint32_t sb = sbase + (uint32_t)(slot * STAGE_BYTES);
#pragma unroll
        for (int i = 0; i < 4; i++) {
            const int seg = tid + i * 256;
            const int ra = seg >> 4, ca = seg & 15;
            cpa16(sb + sw2(ra, ca),
                  Ab + (size_t)(k0 + ra) * LSEQ + row0 + ca * 8);
            const int rb = seg >> 3, cb = seg & 7;
            cpa16(sb + ARR_BYTES + sw_off(rb, cb),
                  W + (size_t)(col0 + rb) * K + k0 + cb * 8);
        }
    };

    load_stage(0, 0);        CP_COMMIT();
    load_stage(1, GK_CHUNK); CP_COMMIT();

    const int at_row  = ((lane >> 4) << 3) + (lane & 7);
    const int at_cs   = (lane >> 3) & 1;
    const int b_row  = (((lane >> 3) & 3) >> 1) * 8 + (lane & 7);
    const int b_half = (lane >> 3) & 1;

    int slot = 0;
    for (int c = 0; c < nchunk; c++) {
        CP_WAIT1();
        __syncthreads();
        if (c + 2 < nchunk) {
            const int nslot = (slot + 2 >= NSTAGE) ? (slot + 2 - NSTAGE) : (slot + 2);
            load_stage(nslot, (c + 2) * GK_CHUNK);
        }
        CP_COMMIT();

        const uint32_t stb = sbase + (uint32_t)(slot * STAGE_BYTES);
#pragma unroll
        for (int step = 0; step < 4; step++) {
            uint32_t af[2][4];
#pragma unroll
            for (int mt = 0; mt < 2; mt++) {
                const int row = step*16 + at_row;
                const int cs  = ((wm*32 + mt*16) >> 3) + at_cs;
                LDSM_X4T(af[mt], stb + sw2(row, cs));
            }
            uint32_t bf[8][2];
#pragma unroll
            for (int p = 0; p < 4; p++) {
                const int r = wn*64 + p*16 + b_row;
                uint32_t t[4];
                LDSM_X4(t, stb + ARR_BYTES + sw_off(r, step*2 + b_half));
                bf[p*2][0]=t[0]; bf[p*2][1]=t[1]; bf[p*2+1][0]=t[2]; bf[p*2+1][1]=t[3];
            }
#pragma unroll
            for (int mt = 0; mt < 2; mt++)
#pragma unroll
                for (int nt = 0; nt < 8; nt++)
                    MMA16816(acc[mt][nt], af[mt], bf[nt]);
        }
        slot = (slot + 1 == NSTAGE) ? 0 : slot + 1;
    }

#pragma unroll
    for (int mt = 0; mt < 2; mt++) {
        const int r0g = row0 + wm*32 + mt*16 + (lane >> 2);
#pragma unroll
        for (int nt = 0; nt < 8; nt++) {
            const int col = col0 + wn*64 + nt*8 + (lane & 3)*2;
            const float b0 = bias[col], b1 = bias[col+1];
            *(float2*)(Cb + (size_t)r0g       * Ntot + col) =
                make_float2(acc[mt][nt][0] + b0, acc[mt][nt][1] + b1);
            *(float2*)(Cb + (size_t)(r0g + 8) * Ntot + col) =
                make_float2(acc[mt][nt][2] + b0, acc[mt][nt][3] + b1);
        }
    }
}

// ---------------------------------------------------------------------------
// k-GEMM: g_kh[d,l] = dot(w3h[d,:64], g_h[l,:64]) — single K=64 stage, fp16 out
// ---------------------------------------------------------------------------
__global__ void __launch_bounds__(256, 2)
kgemm_kernel()
{
    __shared__ char smem[2 * ARR_BYTES];
    const uint32_t sbase = (uint32_t)__cvta_generic_to_shared(smem);
    const int tid  = threadIdx.x;
    const int lane = tid & 31;
    const int wid  = tid >> 5;
    const int wm   = wid & 3;
    const int wn   = wid >> 2;

    const int col0 = blockIdx.x * 128;   // l
    const int row0 = blockIdx.y * 128;   // d

#pragma unroll
    for (int i = 0; i < 4; i++) {
        const int seg = tid + i * 256;
        const int r = seg >> 3, c = seg & 7;
        const uint32_t so = sw_off(r, c);
        cpa16(sbase + so,             g_w3h + (size_t)(row0 + r) * ORDER + c * 8);
        cpa16(sbase + so + ARR_BYTES, g_h   + (size_t)(col0 + r) * ORDER + c * 8);
    }
    CP_COMMIT();
    CP_WAIT0();
    __syncthreads();

    float acc[2][8][4];
#pragma unroll
    for (int i = 0; i < 2; i++)
#pragma unroll
        for (int j = 0; j < 8; j++)
#pragma unroll
            for (int q = 0; q < 4; q++) acc[i][j][q] = 0.f;

    const int a_row  = lane & 15;
    const int a_half = lane >> 4;
    const int b_row  = (((lane >> 3) & 3) >> 1) * 8 + (lane & 7);
    const int b_half = (lane >> 3) & 1;

#pragma unroll
    for (int step = 0; step < 4; step++) {
        uint32_t af[2][4];
#pragma unroll
        for (int mt = 0; mt < 2; mt++) {
            const int r = wm*32 + mt*16 + a_row;
            LDSM_X4(af[mt], sbase + sw_off(r, step*2 + a_half));
        }
        uint32_t bf[8][2];
#pragma unroll
        for (int p = 0; p < 4; p++) {
            const int r = wn*64 + p*16 + b_row;
            uint32_t t[4];
            LDSM_X4(t, sbase + ARR_BYTES + sw_off(r, step*2 + b_half));
            bf[p*2][0]=t[0]; bf[p*2][1]=t[1]; bf[p*2+1][0]=t[2]; bf[p*2+1][1]=t[3];
        }
#pragma unroll
        for (int mt = 0; mt < 2; mt++)
#pragma unroll
            for (int nt = 0; nt < 8; nt++)
                MMA16816(acc[mt][nt], af[mt], bf[nt]);
    }

#pragma unroll
    for (int mt = 0; mt < 2; mt++) {
        const int d = row0 + wm*32 + mt*16 + (lane >> 2);
#pragma unroll
        for (int nt = 0; nt < 8; nt++) {
            const int l = col0 + wn*64 + nt*8 + (lane & 3)*2;
            *(__half2*)(g_kh + (size_t)d       * LSEQ + l) =
                __floats2half2_rn(acc[mt][nt][0], acc[mt][nt][1]);
            *(__half2*)(g_kh + (size_t)(d + 8) * LSEQ + l) =
                __floats2half2_rn(acc[mt][nt][2], acc[mt][nt][3]);
        }
    }
}

// ---------------------------------------------------------------------------
// merged fp32 -> fp16 convert (4 ranges, 1 launch, streaming stores)
// ---------------------------------------------------------------------------
__global__ void __launch_bounds__(256)
tohalf4_kernel(const float4* __restrict__ s0, __half2* __restrict__ d0, int n0,
               const float4* __restrict__ s1, __half2* __restrict__ d1, int n1,
               const float4* __restrict__ s2, __half2* __restrict__ d2, int n2,
               const float4* __restrict__ s3, __half2* __restrict__ d3, int n3)
{
    int i = blockIdx.x * 256 + threadIdx.x;
    const float4* s; __half2* d;
    if (i < n0) { s = s0; d = d0; }
    else if (i < n0 + n1) { i -= n0; s = s1; d = d1; }
    else if (i < n0 + n1 + n2) { i -= n0 + n1; s = s2; d = d2; }
    else if (i < n0 + n1 + n2 + n3) { i -= n0 + n1 + n2; s = s3; d = d3; }
    else return;
    const float4 v = __ldcs(s + i);
    __half2 h0 = __floats2half2_rn(v.x, v.y);
    __half2 h1 = __floats2half2_rn(v.z, v.w);
    __stcs((uint32_t*)(d + i*2),     *(uint32_t*)&h0);
    __stcs((uint32_t*)(d + i*2 + 1), *(uint32_t*)&h1);
}

// ---------------------------------------------------------------------------
// Short conv + transpose + gate — half2 vectorized (64 d per block, 2/thread)
// ---------------------------------------------------------------------------
__global__ void __launch_bounds__(256)
shortconv_kernel(const float* __restrict__ sw, const float* __restrict__ sb)
{
    __shared__ float2 su[3][34][33];   // [gate][l+halo][d-pair]
    const int b = blockIdx.z, l0 = blockIdx.x * 32, d0 = blockIdx.y * 64;
    const int tx = threadIdx.x, ty = threadIdx.y;   // tx: d-pair 0..31, ty: 0..7

#pragma unroll
    for (int g = 0; g < 3; g++)
        for (int li = ty; li < 34; li += 8) {
            const int l = l0 + li - 2;
            float2 v = make_float2(0.f, 0.f);
            if (l >= 0) {
                const __half2 h = *(const __half2*)(g_u +
                    ((size_t)b * LSEQ + l) * D3 + g * DMODEL + d0 + tx * 2);
                v = __half22float2(h);
            }
            su[g][li][tx] = v;
        }
    __syncthreads();

    const int l = l0 + tx;               // tx now indexes l for the output phase
    for (int dp = ty; dp < 32; dp += 8) {
        const int d = d0 + dp * 2;
        float2 r[3];
#pragma unroll
        for (int g = 0; g < 3; g++) {
            const int c = g * DMODEL + d;
            const float w0a = sw[c*3+0],     w1a = sw[c*3+1],     w2a = sw[c*3+2],     ba = sb[c];
            const float w0b = sw[(c+1)*3+0], w1b = sw[(c+1)*3+1], w2b = sw[(c+1)*3+2], bb = sb[c+1];
            const float2 s0 = su[g][tx][dp];
            const float2 s1 = su[g][tx+1][dp];
            const float2 s2 = su[g][tx+2][dp];
            r[g].x = w0a * s0.x + w1a * s1.x + w2a * s2.x + ba;
            r[g].y = w0b * s0.y + w1b * s1.y + w2b * s2.y + bb;
        }
        const size_t o0 = ((size_t)b * DMODEL + d)     * LSEQ + l;
        const size_t o1 = ((size_t)b * DMODEL + d + 1) * LSEQ + l;
        g_x0[o0] = __float2half_rn(r[0].x);
        g_x0[o1] = __float2half_rn(r[0].y);
        g_vg[o0] = __float2half_rn(r[1].x * r[2].x);
        g_vg[o1] = __float2half_rn(r[1].y * r[2].y);
    }
}

// ---------------------------------------------------------------------------
// Filter MLP hidden state h (L,64) -> fp16
// ---------------------------------------------------------------------------
__global__ void __launch_bounds__(256)
filter_h_kernel(const float* __restrict__ w0, const float* __restrict__ b0,
                const float* __restrict__ freq,
                const float* __restrict__ w1, const float* __restrict__ b1,
                const float* __restrict__ w2, const float* __restrict__ b2)
{
    __shared__ float ws[ORDER][ORDER + 1];
    __shared__ float h1[4][ORDER + 1];
    const int o  = threadIdx.x;
    const int lq = threadIdx.y;
    const int l  = blockIdx.x * 4 + lq;
    const int tid = lq * ORDER + o;

    const float t   = (float)l / (float)(LSEQ - 1);
    const float ang = 1e-4f * (2.f * 3.14159265358979323846f * (float)l / (float)LSEQ);
    const float fr = freq[o];
    float v = t * w0[o*3+0] + __cosf(ang) * w0[o*3+1] - __sinf(ang) * w0[o*3+2] + b0[o];
    h1[lq][o] = __sinf(fr * v);
    for (int i = tid; i < ORDER * ORDER; i += 256) ws[i >> 6][i & 63] = w1[i];
    __syncthreads();

    float s = b1[o];
#pragma unroll 8
    for (int j = 0; j < ORDER; j++) s = fmaf(ws[o][j], h1[lq][j], s);
    const float h2v = __sinf(fr * s);
    __syncthreads();

    h1[lq][o] = h2v;
    for (int i = tid; i < ORDER * ORDER; i += 256) ws[i >> 6][i & 63] = w2[i];
    __syncthreads();

    s = b2[o];
#pragma unroll 8
    for (int j = 0; j < ORDER; j++) s = fmaf(ws[o][j], h1[lq][j], s);
    g_h[(size_t)l * ORDER + o] = __float2half_rn(__sinf(fr * s));
}

// ---------------------------------------------------------------------------
// N=8192 in-place FFT (single smem buffer), XOR swizzle
// ---------------------------------------------------------------------------
#define SQ(w) ((w) ^ (((w) >> 4) & 15))

__device__ __forceinline__ float2 cmul(float2 a, float2 b) {
    return make_float2(a.x*b.x - a.y*b.y, a.x*b.y + a.y*b.x);
}

__device__ __forceinline__ void fft_init_tw(float2* tw)
{
    for (int i = threadIdx.x; i < 512; i += FFT_T) {
        float s, c;
        sincosf(-2.f * 3.14159265358979323846f * (float)i / (float)NFFT, &s, &c);
        tw[i] = make_float2(c, s);
    }
}

#define CMC(v, wr, wi) do { float _x=(v).x, _y=(v).y; \
    (v).x = _x*(wr) - _y*(wi); (v).y = _x*(wi) + _y*(wr); } while (0)

__device__ __forceinline__ void bf4(float2& a, float2& b, float2& c, float2& d)
{
    const float2 A = make_float2(a.x + c.x, a.y + c.y);
    const float2 B = make_float2(a.x - c.x, a.y - c.y);
    const float2 Cc = make_float2(b.x + d.x, b.y + d.y);
    const float2 D = make_float2(b.x - d.x, b.y - d.y);
    a = make_float2(A.x + Cc.x, A.y + Cc.y);
    c = make_float2(A.x - Cc.x, A.y - Cc.y);
    b = make_float2(B.x + D.y, B.y - D.x);
    d = make_float2(B.x - D.y, B.y + D.x);
}

__device__ __forceinline__ void dft16(float2* x)
{
    bf4(x[0], x[4], x[8],  x[12]);
    bf4(x[1], x[5], x[9],  x[13]);
    bf4(x[2], x[6], x[10], x[14]);
    bf4(x[3], x[7], x[11], x[15]);
    const float C1 = 0.92387953251128674f, S1 = -0.38268343236508978f;
    const float C2 = 0.70710678118654757f, S2 = -0.70710678118654746f;
    const float C3 = 0.38268343236508984f, S3 = -0.92387953251128674f;
    const float C6 = -0.70710678118654746f, S6 = -0.70710678118654757f;
    const float C9 = -0.92387953251128674f, S9 =  0.38268343236508978f;
    CMC(x[5],  C1, S1);  CMC(x[9],  C2, S2);  CMC(x[13], C3, S3);
    CMC(x[6],  C2, S2);  { float tx = x[10].x; x[10].x = x[10].y; x[10].y = -tx; }  CMC(x[14], C6, S6);
    CMC(x[7],  C3, S3);  CMC(x[11], C6, S6);  CMC(x[15], C9, S9);
    bf4(x[0],  x[1],  x[2],  x[3]);
    bf4(x[4],  x[5],  x[6],  x[7]);
    bf4(x[8],  x[9],  x[10], x[11]);
    bf4(x[12], x[13], x[14], x[15]);
}

__device__ __forceinline__ void r16_stage_ip(float2* buf, const float2* tw, int m)
{
    const int t = threadIdx.x;
    const int k = t & (m - 1);
    const int jm = t - k;
    float2 x[16];
#pragma unroll
    for (int c = 0; c < 16; c++) x[c] = buf[SQ(t + 512 * c)];
    dft16(x);
    const float2 w1 = tw[jm];
    float2 wc = w1;
#pragma unroll
    for (int c = 1; c < 16; c++) {
        const int p = ((c & 3) << 2) | (c >> 2);
        x[p] = cmul(x[p], wc);
        wc = cmul(wc, w1);
    }
    __syncthreads();
    const int ob = 16 * jm + k;
#pragma unroll
    for (int c = 0; c < 16; c++)
        buf[SQ(ob + c * m)] = x[((c & 3) << 2) | (c >> 2)];
    __syncthreads();
}

__device__ __forceinline__ void fft8192_ip(float2* buf, const float2* tw)
{
    __syncthreads();
    r16_stage_ip(buf, tw, 1);
    r16_stage_ip(buf, tw, 16);
    r16_stage_ip(buf, tw, 256);
    const int t = threadIdx.x;
    float2 a[8], b[8];
#pragma unroll
    for (int c = 0; c < 8; c++) {
        const int i = t + 512 * c;
        a[c] = buf[SQ(i)];
        b[c] = buf[SQ(i + 4096)];
    }
    __syncthreads();
#pragma unroll
    for (int c = 0; c < 8; c++) {
        const int i = t + 512 * c;
        buf[SQ(i)]        = make_float2(a[c].x + b[c].x, a[c].y + b[c].y);
        buf[SQ(i + 4096)] = make_float2(a[c].x - b[c].x, a[c].y - b[c].y);
    }
    __syncthreads();
}

// FFT of filter k (applies ExponentialModulation decay at load)
__global__ void __launch_bounds__(FFT_T, 2) fftk_kernel()
{
    extern __shared__ float2 smem_fft[];
    float2* buf = smem_fft;
    float2* tw  = buf + NFFT;
    fft_init_tw(tw);

    const int d0 = blockIdx.x * 2;
    const __half* k0 = g_kh + (size_t)d0 * LSEQ;
    const __half* k1 = k0 + LSEQ;
    const float min_decay = -4.60517018598809136804f / 1.5f;
    const float max_decay = -4.60517018598809136804f / 0.3f;
    const float ad0 = fabsf(min_decay + (max_decay - min_decay) * (float)d0 / (float)(DMODEL - 1));
    const float ad1 = fabsf(min_decay + (max_decay - min_decay) * (float)(d0 + 1) / (float)(DMODEL - 1));

    for (int i = threadIdx.x; i < LSEQ; i += FFT_T) {
        const float t = (float)i / (float)(LSEQ - 1);
        buf[SQ(i)] = make_float2(__half2float(k0[i]) * __expf(-t * ad0),
                                 __half2float(k1[i]) * __expf(-t * ad1));
        buf[SQ(i + LSEQ)] = make_float2(0.f, 0.f);
    }
    fft8192_ip(buf, tw);

    const float hc = 0.5f / (float)NFFT;
    __half2* o0 = g_Kf + (size_t)d0 * NFFT;
    __half2* o1 = o0 + NFFT;
    for (int i = threadIdx.x; i < NFFT; i += FFT_T) {
        const int ir = (NFFT - i) & (NFFT - 1);
        const float2 A = buf[SQ(i)];
        const float2 Zr = buf[SQ(ir)];
        const float sx = A.x + Zr.x, sy = A.y - Zr.y;
        const float px = A.x - Zr.x, py = A.y + Zr.y;
        o0[i] = __floats2half2_rn(sx * hc, sy * hc);
        o1[i] = __floats2half2_rn(py * hc, -px * hc);
    }
}

__device__ __forceinline__ float2 pw_prod(float2 A, float2 B, float2 k)
{
    const float u0x = 0.5f * (A.x + B.x), u0y = 0.5f * (A.y - B.y);
    const float px  = 0.5f * (A.x - B.x), py  = 0.5f * (A.y + B.y);
    const float u1x = py, u1y = -px;
    const float y0x = u0x * k.x - u0y * k.y;
    const float y0y = u0x * k.y + u0y * k.x;
    const float y1x = u1x * k.x - u1y * k.y;
    const float y1y = u1x * k.y + u1y * k.x;
    return make_float2(y0x - y1y, -(y0y + y1x));
}

__global__ void __launch_bounds__(FFT_T, 2) fftconv_kernel(const float* __restrict__ fbias)
{
    extern __shared__ float2 smem_fft[];
    float2* buf = smem_fft;
    float2* tw  = buf + NFFT;
    fft_init_tw(tw);

    const int d = blockIdx.x;
    const __half* v0 = g_vg + (size_t)d * LSEQ;
    const __half* v1 = g_vg + ((size_t)DMODEL + d) * LSEQ;

    for (int i = threadIdx.x; i < LSEQ; i += FFT_T) {
        buf[SQ(i)]        = make_float2(__half2float(v0[i]), __half2float(v1[i]));
        buf[SQ(i + LSEQ)] = make_float2(0.f, 0.f);
    }
    fft8192_ip(buf, tw);

    const __half2* kf = g_Kf + (size_t)d * NFFT;
    const int t = threadIdx.x;
#pragma unroll 1
    for (int c = 0; c < 8; c++) {
        const int i  = t + 512 * c;
        const int ir = (NFFT - i) & (NFFT - 1);
        const float2 A = buf[SQ(i)];
        const float2 B = buf[SQ(ir)];
        buf[SQ(i)] = pw_prod(A, B, __half22float2(kf[i]));
        if (ir != i)
            buf[SQ(ir)] = pw_prod(B, A, __half22float2(kf[ir]));
    }
    if (t == 0) {
        const float2 A = buf[SQ(4096)];
        buf[SQ(4096)] = pw_prod(A, A, __half22float2(kf[4096]));
    }

    fft8192_ip(buf, tw);

    const float fb = fbias[d];
    for (int i = threadIdx.x; i < LSEQ; i += FFT_T) {
        const size_t o0 = (size_t)d * LSEQ + i;
        const size_t o1 = ((size_t)DMODEL + d) * LSEQ + i;
        const float2 r = buf[SQ(i)];
        const float x00 = __half2float(g_x0[o0]);
        const float x01 = __half2float(g_x0[o1]);
        g_y[o0] = __float2half_rn((r.x + __half2float(v0[i]) * fb) * x00);
        g_y[o1] = __float2half_rn((-r.y + __half2float(v1[i]) * fb) * x01);
    }
}

// ---------------------------------------------------------------------------
// Launch (single stream — allocation-free; 8 launches)
// ---------------------------------------------------------------------------
extern "C" void kernel_launch(void* const* d_in, const int* in_sizes, int n_in,
                              void* d_out, int out_size)
{
    (void)in_sizes; (void)n_in; (void)out_size;
    const float* x     = (const float*)d_in[0];
    const float* ipw   = (const float*)d_in[1];
    const float* ipb   = (const float*)d_in[2];
    const float* sw    = (const float*)d_in[3];
    const float* sb    = (const float*)d_in[4];
    const float* w0    = (const float*)d_in[5];
    const float* b0    = (const float*)d_in[6];
    const float* freq  = (const float*)d_in[7];
    const float* w1    = (const float*)d_in[8];
    const float* b1    = (const float*)d_in[9];
    const float* w2    = (const float*)d_in[10];
    const float* b2    = (const float*)d_in[11];
    const float* w3    = (const float*)d_in[12];
    const float* fbias = (const float*)d_in[13];
    const float* opw   = (const float*)d_in[14];
    const float* opb   = (const float*)d_in[15];
    float* out = (float*)d_out;

    cudaFuncSetAttribute(fftk_kernel,    cudaFuncAttributeMaxDynamicSharedMemorySize, FFT_SMEM);
    cudaFuncSetAttribute(fftconv_kernel, cudaFuncAttributeMaxDynamicSharedMemorySize, FFT_SMEM);
    cudaFuncSetAttribute(gemm_nn_kernel, cudaFuncAttributeMaxDynamicSharedMemorySize, GM_SMEM);
    cudaFuncSetAttribute(gemm_tn_kernel, cudaFuncAttributeMaxDynamicSharedMemorySize, GM_SMEM);

    __half *p_a, *p_w1, *p_w2, *p_w3, *p_u, *p_y;
    cudaGetSymbolAddress((void**)&p_a,  g_a);
    cudaGetSymbolAddress((void**)&p_w1, g_w1);
    cudaGetSymbolAddress((void**)&p_w2, g_w2);
    cudaGetSymbolAddress((void**)&p_w3, g_w3h);
    cudaGetSymbolAddress((void**)&p_u,  g_u);
    cudaGetSymbolAddress((void**)&p_y,  g_y);

    // 0) all fp32->fp16 conversions in one launch
    const int n4x  = (BATCH*LSEQ*DMODEL)/4;
    const int n4w1 = (D3*DMODEL)/4;
    const int n4w2 = (DMODEL*DMODEL)/4;
    const int n4w3 = (DMODEL*ORDER)/4;
    tohalf4_kernel<<<(n4x+n4w1+n4w2+n4w3+255)/256, 256>>>(
        (const float4*)x,   (__half2*)p_a,  n4x,
        (const float4*)ipw, (__half2*)p_w1, n4w1,
        (const float4*)opw, (__half2*)p_w2, n4w2,
        (const float4*)w3,  (__half2*)p_w3, n4w3);

    // 1) in_proj GEMM (128x128, 2 CTAs/SM, fp16 out)
    gemm_nn_kernel<<<dim3(D3/128, (BATCH*LSEQ)/128), 256, GM_SMEM>>>(
        p_a, p_w1, ipb, p_u, D3, DMODEL);

    // 2) short conv + transpose + gate (half2 vectorized)
    shortconv_kernel<<<dim3(LSEQ/32, DMODEL/64, BATCH), dim3(32, 8)>>>(sw, sb);

    // 3) filter MLP hidden state (fp16)
    filter_h_kernel<<<LSEQ/4, dim3(ORDER, 4)>>>(w0, b0, freq, w1, b1, w2, b2);

    // 4) k-projection on tensor cores (K=64)
    kgemm_kernel<<<dim3(LSEQ/128, DMODEL/128), 256>>>();

    // 5) FFT of filter k (decay folded in)
    fftk_kernel<<<DMODEL/2, FFT_T, FFT_SMEM>>>();

    // 6) fused FFT conv + bias + output gate
    fftconv_kernel<<<DMODEL, FFT_T, FFT_SMEM>>>(fbias);

    // 7) out_proj GEMM reading g_y transposed
    gemm_tn_kernel<<<dim3(DMODEL/128, LSEQ/128, BATCH), 256, GM_SMEM>>>(
        p_y, p_w2, opb, out, DMODEL, DMODEL,
        (size_t)DMODEL*LSEQ, (size_t)LSEQ*DMODEL);
}

// round 17
// speedup vs baseline: 1.0918x; 1.0087x over previous
#include <cuda_runtime.h>
#include <cuda_fp16.h>
#include <math.h>
#include <stdint.h>

#define BATCH 2
#define LSEQ 4096
#define DMODEL 2048
#define D3 (3*DMODEL)
#define ORDER 64
#define NFFT 8192
#define FFT_T 512
#define FFT_SMEM ((NFFT + 512) * (int)sizeof(float2))   // 69632 B

// ---------------------------------------------------------------------------
// Scratch (device globals)
// ---------------------------------------------------------------------------
__device__ __half g_u [(size_t)BATCH*LSEQ*D3];        // fp16 in_proj output
__device__ __half g_x0[(size_t)BATCH*DMODEL*LSEQ];    // fp16 gate
__device__ __half g_vg[(size_t)BATCH*DMODEL*LSEQ];    // fp16 v*x1
__device__ __half g_y [(size_t)BATCH*DMODEL*LSEQ];    // fp16 post-conv gated (B,D,L)
__device__ __half g_h [(size_t)LSEQ*ORDER];           // fp16 MLP hidden (L,64)
__device__ __half g_kh[(size_t)DMODEL*LSEQ];          // fp16 filter k pre-decay (D,L)
__device__ __half2 g_Kf[(size_t)DMODEL*NFFT];         // fp16 spectrum

__device__ __half g_a  [(size_t)BATCH*LSEQ*DMODEL];   // fp16 x (B,L,D)
__device__ __half g_w1 [(size_t)D3*DMODEL];
__device__ __half g_w2 [(size_t)DMODEL*DMODEL];
__device__ __half g_w3h[(size_t)DMODEL*ORDER];

// ---------------------------------------------------------------------------
// GEMM common
// ---------------------------------------------------------------------------
#define GK_CHUNK 64
#define ARR_BYTES 16384
#define STAGE_BYTES (2*ARR_BYTES)
#define NSTAGE 3
#define GM_SMEM (NSTAGE*STAGE_BYTES)      // 98304 B

__device__ __forceinline__ uint32_t sw_off(int r, int cseg) {
    return (uint32_t)(r * 128 + ((cseg ^ (r & 7)) << 4));
}
__device__ __forceinline__ uint32_t sw2(int r, int cs) {
    return (uint32_t)(r * 256 + ((cs ^ (r & 15)) << 4));
}

__device__ __forceinline__ void cpa16(uint32_t s, const void* g) {
    asm volatile("cp.async.cg.shared.global [%0], [%1], 16;" :: "r"(s), "l"(g));
}
#define CP_COMMIT() asm volatile("cp.async.commit_group;" ::: "memory")
#define CP_WAIT1()  asm volatile("cp.async.wait_group 1;" ::: "memory")
#define CP_WAIT0()  asm volatile("cp.async.wait_group 0;" ::: "memory")

#define LDSM_X4(r, addr) \
    asm volatile("ldmatrix.sync.aligned.m8n8.x4.shared.b16 {%0,%1,%2,%3}, [%4];" \
        : "=r"((r)[0]), "=r"((r)[1]), "=r"((r)[2]), "=r"((r)[3]) : "r"(addr))

#define LDSM_X4T(r, addr) \
    asm volatile("ldmatrix.sync.aligned.m8n8.x4.trans.shared.b16 {%0,%1,%2,%3}, [%4];" \
        : "=r"((r)[0]), "=r"((r)[1]), "=r"((r)[2]), "=r"((r)[3]) : "r"(addr))

#define MMA16816(c, a, b) \
    asm volatile("mma.sync.aligned.m16n8k16.row.col.f32.f16.f16.f32 " \
        "{%0,%1,%2,%3}, {%4,%5,%6,%7}, {%8,%9}, {%0,%1,%2,%3};" \
        : "+f"((c)[0]), "+f"((c)[1]), "+f"((c)[2]), "+f"((c)[3]) \
        : "r"((a)[0]), "r"((a)[1]), "r"((a)[2]), "r"((a)[3]), \
          "r"((b)[0]), "r"((b)[1]))

// ---------------------------------------------------------------------------
// GEMM 1: A row-major (L,K) fp16 -> C fp16 (128x128, 256 thr, 2 CTAs/SM)
// ---------------------------------------------------------------------------
__global__ void __launch_bounds__(256, 2)
gemm_nn_kernel(const __half* __restrict__ A, const __half* __restrict__ W,
               const float* __restrict__ bias, __half* __restrict__ C,
               int Ntot, int K)
{
    extern __shared__ char smem[];
    const uint32_t sbase = (uint32_t)__cvta_generic_to_shared(smem);
    const int tid  = threadIdx.x;
    const int lane = tid & 31;
    const int wid  = tid >> 5;
    const int wm   = wid & 3;
    const int wn   = wid >> 2;

    const int col0 = blockIdx.x * 128;
    const int row0 = blockIdx.y * 128;
    const int nchunk = K / GK_CHUNK;

    float acc[2][8][4];
#pragma unroll
    for (int i = 0; i < 2; i++)
#pragma unroll
        for (int j = 0; j < 8; j++)
#pragma unroll
            for (int q = 0; q < 4; q++) acc[i][j][q] = 0.f;

    auto load_stage = [&](int slot, int k0) {
        const uint32_t sb = sbase + (uint32_t)(slot * STAGE_BYTES);
#pragma unroll
        for (int i = 0; i < 4; i++) {
            const int seg = tid + i * 256;
            const int r = seg >> 3, c = seg & 7;
            const uint32_t so = sw_off(r, c);
            cpa16(sb + so,             A + (size_t)(row0 + r) * K + k0 + c * 8);
            cpa16(sb + so + ARR_BYTES, W + (size_t)(col0 + r) * K + k0 + c * 8);
        }
    };

    load_stage(0, 0);        CP_COMMIT();
    load_stage(1, GK_CHUNK); CP_COMMIT();

    const int a_row  = lane & 15;
    const int a_half = lane >> 4;
    const int b_row  = (((lane >> 3) & 3) >> 1) * 8 + (lane & 7);
    const int b_half = (lane >> 3) & 1;

    int slot = 0;
    for (int c = 0; c < nchunk; c++) {
        CP_WAIT1();
        __syncthreads();
        if (c + 2 < nchunk) {
            const int nslot = (slot + 2 >= NSTAGE) ? (slot + 2 - NSTAGE) : (slot + 2);
            load_stage(nslot, (c + 2) * GK_CHUNK);
        }
        CP_COMMIT();

        const uint32_t stb = sbase + (uint32_t)(slot * STAGE_BYTES);
#pragma unroll
        for (int step = 0; step < 4; step++) {
            uint32_t af[2][4];
#pragma unroll
            for (int mt = 0; mt < 2; mt++) {
                const int r = wm*32 + mt*16 + a_row;
                LDSM_X4(af[mt], stb + sw_off(r, step*2 + a_half));
            }
            uint32_t bf[8][2];
#pragma unroll
            for (int p = 0; p < 4; p++) {
                const int r = wn*64 + p*16 + b_row;
                uint32_t t[4];
                LDSM_X4(t, stb + ARR_BYTES + sw_off(r, step*2 + b_half));
                bf[p*2][0]=t[0]; bf[p*2][1]=t[1]; bf[p*2+1][0]=t[2]; bf[p*2+1][1]=t[3];
            }
#pragma unroll
            for (int mt = 0; mt < 2; mt++)
#pragma unroll
                for (int nt = 0; nt < 8; nt++)
                    MMA16816(acc[mt][nt], af[mt], bf[nt]);
        }
        slot = (slot + 1 == NSTAGE) ? 0 : slot + 1;
    }

#pragma unroll
    for (int mt = 0; mt < 2; mt++) {
        const int r0g = row0 + wm*32 + mt*16 + (lane >> 2);
#pragma unroll
        for (int nt = 0; nt < 8; nt++) {
            const int col = col0 + wn*64 + nt*8 + (lane & 3)*2;
            const float b0 = bias[col], b1 = bias[col+1];
            *(__half2*)(C + (size_t)r0g       * Ntot + col) =
                __floats2half2_rn(acc[mt][nt][0] + b0, acc[mt][nt][1] + b1);
            *(__half2*)(C + (size_t)(r0g + 8) * Ntot + col) =
                __floats2half2_rn(acc[mt][nt][2] + b0, acc[mt][nt][3] + b1);
        }
    }
}

// ---------------------------------------------------------------------------
// GEMM 2: A stored transposed (K=d rows, M=l cols) fp16 (= g_y), trans-ldmatrix
// ---------------------------------------------------------------------------
__global__ void __launch_bounds__(256, 2)
gemm_tn_kernel(const __half* __restrict__ At, const __half* __restrict__ W,
               const float* __restrict__ bias, float* __restrict__ C,
               int Ntot, int K, size_t strideA, size_t strideC)
{
    extern __shared__ char smem[];
    const uint32_t sbase = (uint32_t)__cvta_generic_to_shared(smem);
    const int tid  = threadIdx.x;
    const int lane = tid & 31;
    const int wid  = tid >> 5;
    const int wm   = wid & 3;
    const int wn   = wid >> 2;

    const int z = blockIdx.z;
    const __half* Ab = At + (size_t)z * strideA;
    float* Cb = C + (size_t)z * strideC;

    const int col0 = blockIdx.x * 128;
    const int row0 = blockIdx.y * 128;
    const int nchunk = K / GK_CHUNK;

    float acc[2][8][4];
#pragma unroll
    for (int i = 0; i < 2; i++)
#pragma unroll
        for (int j = 0; j < 8; j++)
#pragma unroll
            for (int q = 0; q < 4; q++) acc[i][j][q] = 0.f;

    auto load_stage = [&](int slot, int k0) {
        const uint32_t sb = sbase + (uint32_t)(slot * STAGE_BYTES);
#pragma unroll
        for (int i = 0; i < 4; i++) {
            const int seg = tid + i * 256;
            const int ra = seg >> 4, ca = seg & 15;
            cpa16(sb + sw2(ra, ca),
                  Ab + (size_t)(k0 + ra) * LSEQ + row0 + ca * 8);
            const int rb = seg >> 3, cb = seg & 7;
            cpa16(sb + ARR_BYTES + sw_off(rb, cb),
                  W + (size_t)(col0 + rb) * K + k0 + cb * 8);
        }
    };

    load_stage(0, 0);        CP_COMMIT();
    load_stage(1, GK_CHUNK); CP_COMMIT();

    const int at_row  = ((lane >> 4) << 3) + (lane & 7);
    const int at_cs   = (lane >> 3) & 1;
    const int b_row  = (((lane >> 3) & 3) >> 1) * 8 + (lane & 7);
    const int b_half = (lane >> 3) & 1;

    int slot = 0;
    for (int c = 0; c < nchunk; c++) {
        CP_WAIT1();
        __syncthreads();
        if (c + 2 < nchunk) {
            const int nslot = (slot + 2 >= NSTAGE) ? (slot + 2 - NSTAGE) : (slot + 2);
            load_stage(nslot, (c + 2) * GK_CHUNK);
        }
        CP_COMMIT();

        const uint32_t stb = sbase + (uint32_t)(slot * STAGE_BYTES);
#pragma unroll
        for (int step = 0; step < 4; step++) {
            uint32_t af[2][4];
#pragma unroll
            for (int mt = 0; mt < 2; mt++) {
                const int row = step*16 + at_row;
                const int cs  = ((wm*32 + mt*16) >> 3) + at_cs;
                LDSM_X4T(af[mt], stb + sw2(row, cs));
            }
            uint32_t bf[8][2];
#pragma unroll
            for (int p = 0; p < 4; p++) {
                const int r = wn*64 + p*16 + b_row;
                uint32_t t[4];
                LDSM_X4(t, stb + ARR_BYTES + sw_off(r, step*2 + b_half));
                bf[p*2][0]=t[0]; bf[p*2][1]=t[1]; bf[p*2+1][0]=t[2]; bf[p*2+1][1]=t[3];
            }
#pragma unroll
            for (int mt = 0; mt < 2; mt++)
#pragma unroll
                for (int nt = 0; nt < 8; nt++)
                    MMA16816(acc[mt][nt], af[mt], bf[nt]);
        }
        slot = (slot + 1 == NSTAGE) ? 0 : slot + 1;
    }

#pragma unroll
    for (int mt = 0; mt < 2; mt++) {
        const int r0g = row0 + wm*32 + mt*16 + (lane >> 2);
#pragma unroll
        for (int nt = 0; nt < 8; nt++) {
            const int col = col0 + wn*64 + nt*8 + (lane & 3)*2;
            const float b0 = bias[col], b1 = bias[col+1];
            *(float2*)(Cb + (size_t)r0g       * Ntot + col) =
                make_float2(acc[mt][nt][0] + b0, acc[mt][nt][1] + b1);
            *(float2*)(Cb + (size_t)(r0g + 8) * Ntot + col) =
                make_float2(acc[mt][nt][2] + b0, acc[mt][nt][3] + b1);
        }
    }
}

// ---------------------------------------------------------------------------
// k-GEMM: g_kh[d,l] = dot(w3h[d,:64], g_h[l,:64]) — single K=64 stage, fp16 out
// ---------------------------------------------------------------------------
__global__ void __launch_bounds__(256, 2)
kgemm_kernel()
{
    __shared__ char smem[2 * ARR_BYTES];
    const uint32_t sbase = (uint32_t)__cvta_generic_to_shared(smem);
    const int tid  = threadIdx.x;
    const int lane = tid & 31;
    const int wid  = tid >> 5;
    const int wm   = wid & 3;
    const int wn   = wid >> 2;

    const int col0 = blockIdx.x * 128;   // l
    const int row0 = blockIdx.y * 128;   // d

#pragma unroll
    for (int i = 0; i < 4; i++) {
        const int seg = tid + i * 256;
        const int r = seg >> 3, c = seg & 7;
        const uint32_t so = sw_off(r, c);
        cpa16(sbase + so,             g_w3h + (size_t)(row0 + r) * ORDER + c * 8);
        cpa16(sbase + so + ARR_BYTES, g_h   + (size_t)(col0 + r) * ORDER + c * 8);
    }
    CP_COMMIT();
    CP_WAIT0();
    __syncthreads();

    float acc[2][8][4];
#pragma unroll
    for (int i = 0; i < 2; i++)
#pragma unroll
        for (int j = 0; j < 8; j++)
#pragma unroll
            for (int q = 0; q < 4; q++) acc[i][j][q] = 0.f;

    const int a_row  = lane & 15;
    const int a_half = lane >> 4;
    const int b_row  = (((lane >> 3) & 3) >> 1) * 8 + (lane & 7);
    const int b_half = (lane >> 3) & 1;

#pragma unroll
    for (int step = 0; step < 4; step++) {
        uint32_t af[2][4];
#pragma unroll
        for (int mt = 0; mt < 2; mt++) {
            const int r = wm*32 + mt*16 + a_row;
            LDSM_X4(af[mt], sbase + sw_off(r, step*2 + a_half));
        }
        uint32_t bf[8][2];
#pragma unroll
        for (int p = 0; p < 4; p++) {
            const int r = wn*64 + p*16 + b_row;
            uint32_t t[4];
            LDSM_X4(t, sbase + ARR_BYTES + sw_off(r, step*2 + b_half));
            bf[p*2][0]=t[0]; bf[p*2][1]=t[1]; bf[p*2+1][0]=t[2]; bf[p*2+1][1]=t[3];
        }
#pragma unroll
        for (int mt = 0; mt < 2; mt++)
#pragma unroll
            for (int nt = 0; nt < 8; nt++)
                MMA16816(acc[mt][nt], af[mt], bf[nt]);
    }

#pragma unroll
    for (int mt = 0; mt < 2; mt++) {
        const int d = row0 + wm*32 + mt*16 + (lane >> 2);
#pragma unroll
        for (int nt = 0; nt < 8; nt++) {
            const int l = col0 + wn*64 + nt*8 + (lane & 3)*2;
            *(__half2*)(g_kh + (size_t)d       * LSEQ + l) =
                __floats2half2_rn(acc[mt][nt][0], acc[mt][nt][1]);
            *(__half2*)(g_kh + (size_t)(d + 8) * LSEQ + l) =
                __floats2half2_rn(acc[mt][nt][2], acc[mt][nt][3]);
        }
    }
}

// ---------------------------------------------------------------------------
// merged fp32 -> fp16 convert (4 ranges, 1 launch, streaming stores)
// ---------------------------------------------------------------------------
__global__ void __launch_bounds__(256)
tohalf4_kernel(const float4* __restrict__ s0, __half2* __restrict__ d0, int n0,
               const float4* __restrict__ s1, __half2* __restrict__ d1, int n1,
               const float4* __restrict__ s2, __half2* __restrict__ d2, int n2,
               const float4* __restrict__ s3, __half2* __restrict__ d3, int n3)
{
    int i = blockIdx.x * 256 + threadIdx.x;
    const float4* s; __half2* d;
    if (i < n0) { s = s0; d = d0; }
    else if (i < n0 + n1) { i -= n0; s = s1; d = d1; }
    else if (i < n0 + n1 + n2) { i -= n0 + n1; s = s2; d = d2; }
    else if (i < n0 + n1 + n2 + n3) { i -= n0 + n1 + n2; s = s3; d = d3; }
    else return;
    const float4 v = __ldcs(s + i);
    __half2 h0 = __floats2half2_rn(v.x, v.y);
    __half2 h1 = __floats2half2_rn(v.z, v.w);
    __stcs((uint32_t*)(d + i*2),     *(uint32_t*)&h0);
    __stcs((uint32_t*)(d + i*2 + 1), *(uint32_t*)&h1);
}

// ---------------------------------------------------------------------------
// Short conv + transpose + gate — half2 vectorized (64 d per block, 2/thread)
// ---------------------------------------------------------------------------
__global__ void __launch_bounds__(256)
shortconv_kernel(const float* __restrict__ sw, const float* __restrict__ sb)
{
    __shared__ float2 su[3][34][33];
    const int b = blockIdx.z, l0 = blockIdx.x * 32, d0 = blockIdx.y * 64;
    const int tx = threadIdx.x, ty = threadIdx.y;

#pragma unroll
    for (int g = 0; g < 3; g++)
        for (int li = ty; li < 34; li += 8) {
            const int l = l0 + li - 2;
            float2 v = make_float2(0.f, 0.f);
            if (l >= 0) {
                const __half2 h = *(const __half2*)(g_u +
                    ((size_t)b * LSEQ + l) * D3 + g * DMODEL + d0 + tx * 2);
                v = __half22float2(h);
            }
            su[g][li][tx] = v;
        }
    __syncthreads();

    const int l = l0 + tx;
    for (int dp = ty; dp < 32; dp += 8) {
        const int d = d0 + dp * 2;
        float2 r[3];
#pragma unroll
        for (int g = 0; g < 3; g++) {
            const int c = g * DMODEL + d;
            const float w0a = sw[c*3+0],     w1a = sw[c*3+1],     w2a = sw[c*3+2],     ba = sb[c];
            const float w0b = sw[(c+1)*3+0], w1b = sw[(c+1)*3+1], w2b = sw[(c+1)*3+2], bb = sb[c+1];
            const float2 s0 = su[g][tx][dp];
            const float2 s1 = su[g][tx+1][dp];
            const float2 s2 = su[g][tx+2][dp];
            r[g].x = w0a * s0.x + w1a * s1.x + w2a * s2.x + ba;
            r[g].y = w0b * s0.y + w1b * s1.y + w2b * s2.y + bb;
        }
        const size_t o0 = ((size_t)b * DMODEL + d)     * LSEQ + l;
        const size_t o1 = ((size_t)b * DMODEL + d + 1) * LSEQ + l;
        g_x0[o0] = __float2half_rn(r[0].x);
        g_x0[o1] = __float2half_rn(r[0].y);
        g_vg[o0] = __float2half_rn(r[1].x * r[2].x);
        g_vg[o1] = __float2half_rn(r[1].y * r[2].y);
    }
}

// ---------------------------------------------------------------------------
// Filter MLP hidden state h (L,64) -> fp16
// ---------------------------------------------------------------------------
__global__ void __launch_bounds__(256)
filter_h_kernel(const float* __restrict__ w0, const float* __restrict__ b0,
                const float* __restrict__ freq,
                const float* __restrict__ w1, const float* __restrict__ b1,
                const float* __restrict__ w2, const float* __restrict__ b2)
{
    __shared__ float ws[ORDER][ORDER + 1];
    __shared__ float h1[4][ORDER + 1];
    const int o  = threadIdx.x;
    const int lq = threadIdx.y;
    const int l  = blockIdx.x * 4 + lq;
    const int tid = lq * ORDER + o;

    const float t   = (float)l / (float)(LSEQ - 1);
    const float ang = 1e-4f * (2.f * 3.14159265358979323846f * (float)l / (float)LSEQ);
    const float fr = freq[o];
    float v = t * w0[o*3+0] + __cosf(ang) * w0[o*3+1] - __sinf(ang) * w0[o*3+2] + b0[o];
    h1[lq][o] = __sinf(fr * v);
    for (int i = tid; i < ORDER * ORDER; i += 256) ws[i >> 6][i & 63] = w1[i];
    __syncthreads();

    float s = b1[o];
#pragma unroll 8
    for (int j = 0; j < ORDER; j++) s = fmaf(ws[o][j], h1[lq][j], s);
    const float h2v = __sinf(fr * s);
    __syncthreads();

    h1[lq][o] = h2v;
    for (int i = tid; i < ORDER * ORDER; i += 256) ws[i >> 6][i & 63] = w2[i];
    __syncthreads();

    s = b2[o];
#pragma unroll 8
    for (int j = 0; j < ORDER; j++) s = fmaf(ws[o][j], h1[lq][j], s);
    g_h[(size_t)l * ORDER + o] = __float2half_rn(__sinf(fr * s));
}

// ---------------------------------------------------------------------------
// N=8192 in-place FFT (single smem buffer), XOR swizzle.
// Forward variant assumes input only in [0,4096) (upper half = implicit 0).
// ---------------------------------------------------------------------------
#define SQ(w) ((w) ^ (((w) >> 4) & 15))

__device__ __forceinline__ float2 cmul(float2 a, float2 b) {
    return make_float2(a.x*b.x - a.y*b.y, a.x*b.y + a.y*b.x);
}

__device__ __forceinline__ void fft_init_tw(float2* tw)
{
    for (int i = threadIdx.x; i < 512; i += FFT_T) {
        float s, c;
        sincosf(-2.f * 3.14159265358979323846f * (float)i / (float)NFFT, &s, &c);
        tw[i] = make_float2(c, s);
    }
}

#define CMC(v, wr, wi) do { float _x=(v).x, _y=(v).y; \
    (v).x = _x*(wr) - _y*(wi); (v).y = _x*(wi) + _y*(wr); } while (0)

__device__ __forceinline__ void bf4(float2& a, float2& b, float2& c, float2& d)
{
    const float2 A = make_float2(a.x + c.x, a.y + c.y);
    const float2 B = make_float2(a.x - c.x, a.y - c.y);
    const float2 Cc = make_float2(b.x + d.x, b.y + d.y);
    const float2 D = make_float2(b.x - d.x, b.y - d.y);
    a = make_float2(A.x + Cc.x, A.y + Cc.y);
    c = make_float2(A.x - Cc.x, A.y - Cc.y);
    b = make_float2(B.x + D.y, B.y - D.x);
    d = make_float2(B.x - D.y, B.y + D.x);
}

// second half of dft16 (stage twiddles + final bf4 layer)
__device__ __forceinline__ void dft16_tail(float2* x)
{
    const float C1 = 0.92387953251128674f, S1 = -0.38268343236508978f;
    const float C2 = 0.70710678118654757f, S2 = -0.70710678118654746f;
    const float C3 = 0.38268343236508984f, S3 = -0.92387953251128674f;
    const float C6 = -0.70710678118654746f, S6 = -0.70710678118654757f;
    const float C9 = -0.92387953251128674f, S9 =  0.38268343236508978f;
    CMC(x[5],  C1, S1);  CMC(x[9],  C2, S2);  CMC(x[13], C3, S3);
    CMC(x[6],  C2, S2);  { float tx = x[10].x; x[10].x = x[10].y; x[10].y = -tx; }  CMC(x[14], C6, S6);
    CMC(x[7],  C3, S3);  CMC(x[11], C6, S6);  CMC(x[15], C9, S9);
    bf4(x[0],  x[1],  x[2],  x[3]);
    bf4(x[4],  x[5],  x[6],  x[7]);
    bf4(x[8],  x[9],  x[10], x[11]);
    bf4(x[12], x[13], x[14], x[15]);
}

__device__ __forceinline__ void dft16(float2* x)
{
    bf4(x[0], x[4], x[8],  x[12]);
    bf4(x[1], x[5], x[9],  x[13]);
    bf4(x[2], x[6], x[10], x[14]);
    bf4(x[3], x[7], x[11], x[15]);
    dft16_tail(x);
}

// layer-1 specialized for x[8..15] == 0 (only x[0..7] populated)
__device__ __forceinline__ void dft16_zp(float2* x)
{
#pragma unroll
    for (int j = 0; j < 4; j++) {
        const float2 u = x[j], v = x[j + 4];
        x[j]      = make_float2(u.x + v.x, u.y + v.y);       // u + v
        x[j + 4]  = make_float2(u.x + v.y, u.y - v.x);       // u - i v
        x[j + 8]  = make_float2(u.x - v.x, u.y - v.y);       // u - v
        x[j + 12] = make_float2(u.x - v.y, u.y + v.x);       // u + i v
    }
    dft16_tail(x);
}

__device__ __forceinline__ void r16_store(float2* buf, float2* x,
                                          const float2* tw, int m)
{
    const int t = threadIdx.x;
    const int k = t & (m - 1);
    const int jm = t - k;
    const float2 w1 = tw[jm];
    float2 wc = w1;
#pragma unroll
    for (int c = 1; c < 16; c++) {
        const int p = ((c & 3) << 2) | (c >> 2);
        x[p] = cmul(x[p], wc);
        wc = cmul(wc, w1);
    }
    __syncthreads();
    const int ob = 16 * jm + k;
#pragma unroll
    for (int c = 0; c < 16; c++)
        buf[SQ(ob + c * m)] = x[((c & 3) << 2) | (c >> 2)];
    __syncthreads();
}

__device__ __forceinline__ void r16_stage_ip(float2* buf, const float2* tw, int m)
{
    const int t = threadIdx.x;
    float2 x[16];
#pragma unroll
    for (int c = 0; c < 16; c++) x[c] = buf[SQ(t + 512 * c)];
    dft16(x);
    r16_store(buf, x, tw, m);
}

// stage 1 with zero-padded input: load only lower 4096
__device__ __forceinline__ void r16_stage1_zp(float2* buf, const float2* tw)
{
    const int t = threadIdx.x;
    float2 x[16];
#pragma unroll
    for (int c = 0; c < 8; c++) x[c] = buf[SQ(t + 512 * c)];
    dft16_zp(x);
    r16_store(buf, x, tw, 1);
}

template<bool LOWONLY>
__device__ __forceinline__ void fft_tail_r2(float2* buf)
{
    const int t = threadIdx.x;
    float2 a[8], b[8];
#pragma unroll
    for (int c = 0; c < 8; c++) {
        const int i = t + 512 * c;
        a[c] = buf[SQ(i)];
        b[c] = buf[SQ(i + 4096)];
    }
    __syncthreads();
#pragma unroll
    for (int c = 0; c < 8; c++) {
        const int i = t + 512 * c;
        buf[SQ(i)] = make_float2(a[c].x + b[c].x, a[c].y + b[c].y);
        if (!LOWONLY)
            buf[SQ(i + 4096)] = make_float2(a[c].x - b[c].x, a[c].y - b[c].y);
    }
    __syncthreads();
}

// forward FFT of zero-padded input (valid data only in [0,4096))
__device__ __forceinline__ void fft8192_fwd(float2* buf, const float2* tw)
{
    __syncthreads();
    r16_stage1_zp(buf, tw);
    r16_stage_ip(buf, tw, 16);
    r16_stage_ip(buf, tw, 256);
    fft_tail_r2<false>(buf);
}

// full FFT; LOWONLY skips the never-read upper-half output stores
template<bool LOWONLY>
__device__ __forceinline__ void fft8192_full(float2* buf, const float2* tw)
{
    __syncthreads();
    r16_stage_ip(buf, tw, 1);
    r16_stage_ip(buf, tw, 16);
    r16_stage_ip(buf, tw, 256);
    fft_tail_r2<LOWONLY>(buf);
}

// FFT of filter k (applies ExponentialModulation decay at load)
__global__ void __launch_bounds__(FFT_T, 2) fftk_kernel()
{
    extern __shared__ float2 smem_fft[];
    float2* buf = smem_fft;
    float2* tw  = buf + NFFT;
    fft_init_tw(tw);

    const int d0 = blockIdx.x * 2;
    const __half* k0 = g_kh + (size_t)d0 * LSEQ;
    const __half* k1 = k0 + LSEQ;
    const float min_decay = -4.60517018598809136804f / 1.5f;
    const float max_decay = -4.60517018598809136804f / 0.3f;
    const float ad0 = fabsf(min_decay + (max_decay - min_decay) * (float)d0 / (float)(DMODEL - 1));
    const float ad1 = fabsf(min_decay + (max_decay - min_decay) * (float)(d0 + 1) / (float)(DMODEL - 1));

    for (int i = threadIdx.x; i < LSEQ; i += FFT_T) {
        const float t = (float)i / (float)(LSEQ - 1);
        buf[SQ(i)] = make_float2(__half2float(k0[i]) * __expf(-t * ad0),
                                 __half2float(k1[i]) * __expf(-t * ad1));
    }
    fft8192_fwd(buf, tw);

    const float hc = 0.5f / (float)NFFT;
    __half2* o0 = g_Kf + (size_t)d0 * NFFT;
    __half2* o1 = o0 + NFFT;
    for (int i = threadIdx.x; i < NFFT; i += FFT_T) {
        const int ir = (NFFT - i) & (NFFT - 1);
        const float2 A = buf[SQ(i)];
        const float2 Zr = buf[SQ(ir)];
        const float sx = A.x + Zr.x, sy = A.y - Zr.y;
        const float px = A.x - Zr.x, py = A.y + Zr.y;
        o0[i] = __floats2half2_rn(sx * hc, sy * hc);
        o1[i] = __floats2half2_rn(py * hc, -px * hc);
    }
}

__device__ __forceinline__ float2 pw_prod(float2 A, float2 B, float2 k)
{
    const float u0x = 0.5f * (A.x + B.x), u0y = 0.5f * (A.y - B.y);
    const float px  = 0.5f * (A.x - B.x), py  = 0.5f * (A.y + B.y);
    const float u1x = py, u1y = -px;
    const float y0x = u0x * k.x - u0y * k.y;
    const float y0y = u0x * k.y + u0y * k.x;
    const float y1x = u1x * k.x - u1y * k.y;
    const float y1y = u1x * k.y + u1y * k.x;
    return make_float2(y0x - y1y, -(y0y + y1x));
}

__global__ void __launch_bounds__(FFT_T, 2) fftconv_kernel(const float* __restrict__ fbias)
{
    extern __shared__ float2 smem_fft[];
    float2* buf = smem_fft;
    float2* tw  = buf + NFFT;
    fft_init_tw(tw);

    const int d = blockIdx.x;
    const __half* v0 = g_vg + (size_t)d * LSEQ;
    const __half* v1 = g_vg + ((size_t)DMODEL + d) * LSEQ;

    for (int i = threadIdx.x; i < LSEQ; i += FFT_T) {
        buf[SQ(i)] = make_float2(__half2float(v0[i]), __half2float(v1[i]));
    }
    fft8192_fwd(buf, tw);

    const __half2* kf = g_Kf + (size_t)d * NFFT;
    const int t = threadIdx.x;
#pragma unroll 1
    for (int c = 0; c < 8; c++) {
        const int i  = t + 512 * c;
        const int ir = (NFFT - i) & (NFFT - 1);
        const float2 A = buf[SQ(i)];
        const float2 B = buf[SQ(ir)];
        buf[SQ(i)] = pw_prod(A, B, __half22float2(kf[i]));
        if (ir != i)
            buf[SQ(ir)] = pw_prod(B, A, __half22float2(kf[ir]));
    }
    if (t == 0) {
        const float2 A = buf[SQ(4096)];
        buf[SQ(4096)] = pw_prod(A, A, __half22float2(kf[4096]));
    }

    fft8192_full<true>(buf, tw);   // inverse; only lower half consumed

    const float fb = fbias[d];
    for (int i = threadIdx.x; i < LSEQ; i += FFT_T) {
        const size_t o0 = (size_t)d * LSEQ + i;
        const size_t o1 = ((size_t)DMODEL + d) * LSEQ + i;
        const float2 r = buf[SQ(i)];
        const float x00 = __half2float(g_x0[o0]);
        const float x01 = __half2float(g_x0[o1]);
        g_y[o0] = __float2half_rn((r.x + __half2float(v0[i]) * fb) * x00);
        g_y[o1] = __float2half_rn((-r.y + __half2float(v1[i]) * fb) * x01);
    }
}

// ---------------------------------------------------------------------------
// Launch (single stream — allocation-free; 8 launches)
// ---------------------------------------------------------------------------
extern "C" void kernel_launch(void* const* d_in, const int* in_sizes, int n_in,
                              void* d_out, int out_size)
{
    (void)in_sizes; (void)n_in; (void)out_size;
    const float* x     = (const float*)d_in[0];
    const float* ipw   = (const float*)d_in[1];
    const float* ipb   = (const float*)d_in[2];
    const float* sw    = (const float*)d_in[3];
    const float* sb    = (const float*)d_in[4];
    const float* w0    = (const float*)d_in[5];
    const float* b0    = (const float*)d_in[6];
    const float* freq  = (const float*)d_in[7];
    const float* w1    = (const float*)d_in[8];
    const float* b1    = (const float*)d_in[9];
    const float* w2    = (const float*)d_in[10];
    const float* b2    = (const float*)d_in[11];
    const float* w3    = (const float*)d_in[12];
    const float* fbias = (const float*)d_in[13];
    const float* opw   = (const float*)d_in[14];
    const float* opb   = (const float*)d_in[15];
    float* out = (float*)d_out;

    cudaFuncSetAttribute(fftk_kernel,    cudaFuncAttributeMaxDynamicSharedMemorySize, FFT_SMEM);
    cudaFuncSetAttribute(fftconv_kernel, cudaFuncAttributeMaxDynamicSharedMemorySize, FFT_SMEM);
    cudaFuncSetAttribute(gemm_nn_kernel, cudaFuncAttributeMaxDynamicSharedMemorySize, GM_SMEM);
    cudaFuncSetAttribute(gemm_tn_kernel, cudaFuncAttributeMaxDynamicSharedMemorySize, GM_SMEM);

    __half *p_a, *p_w1, *p_w2, *p_w3, *p_u, *p_y;
    cudaGetSymbolAddress((void**)&p_a,  g_a);
    cudaGetSymbolAddress((void**)&p_w1, g_w1);
    cudaGetSymbolAddress((void**)&p_w2, g_w2);
    cudaGetSymbolAddress((void**)&p_w3, g_w3h);
    cudaGetSymbolAddress((void**)&p_u,  g_u);
    cudaGetSymbolAddress((void**)&p_y,  g_y);

    // 0) all fp32->fp16 conversions in one launch
    const int n4x  = (BATCH*LSEQ*DMODEL)/4;
    const int n4w1 = (D3*DMODEL)/4;
    const int n4w2 = (DMODEL*DMODEL)/4;
    const int n4w3 = (DMODEL*ORDER)/4;
    tohalf4_kernel<<<(n4x+n4w1+n4w2+n4w3+255)/256, 256>>>(
        (const float4*)x,   (__half2*)p_a,  n4x,
        (const float4*)ipw, (__half2*)p_w1, n4w1,
        (const float4*)opw, (__half2*)p_w2, n4w2,
        (const float4*)w3,  (__half2*)p_w3, n4w3);

    // 1) in_proj GEMM (128x128, 2 CTAs/SM, fp16 out)
    gemm_nn_kernel<<<dim3(D3/128, (BATCH*LSEQ)/128), 256, GM_SMEM>>>(
        p_a, p_w1, ipb, p_u, D3, DMODEL);

    // 2) short conv + transpose + gate (half2 vectorized)
    shortconv_kernel<<<dim3(LSEQ/32, DMODEL/64, BATCH), dim3(32, 8)>>>(sw, sb);

    // 3) filter MLP hidden state (fp16)
    filter_h_kernel<<<LSEQ/4, dim3(ORDER, 4)>>>(w0, b0, freq, w1, b1, w2, b2);

    // 4) k-projection on tensor cores (K=64)
    kgemm_kernel<<<dim3(LSEQ/128, DMODEL/128), 256>>>();

    // 5) FFT of filter k (decay folded in, zero-pad pruned)
    fftk_kernel<<<DMODEL/2, FFT_T, FFT_SMEM>>>();

    // 6) fused FFT conv + bias + output gate (pruned forward + inverse)
    fftconv_kernel<<<DMODEL, FFT_T, FFT_SMEM>>>(fbias);

    // 7) out_proj GEMM reading g_y transposed
    gemm_tn_kernel<<<dim3(DMODEL/128, LSEQ/128, BATCH), 256, GM_SMEM>>>(
        p_y, p_w2, opb, out, DMODEL, DMODEL,
        (size_t)DMODEL*LSEQ, (size_t)LSEQ*DMODEL);
}